// round 1
// baseline (speedup 1.0000x reference)
#include <cuda_runtime.h>
#include <cstdint>
#include <math.h>

#define FULL 0xffffffffu

static const int NN  = 50000;
static const int NE  = 500000;
static const int D   = 128;
static const int NRL = 51;
static const int KD  = 1664;   // 13*128
static const int BQ  = 1024;
static const int KQ  = 32;

// ---------------- scratch (device globals; no runtime allocation) ----------------
__device__ float g_x[NN * D];            // current node features (25.6 MB)
__device__ float g_feats[NN * 4 * D];    // [N][4][128] mean,max,min,std (102.4 MB)
__device__ float g_scales[NN * 3];       // PNA scalers per node
__device__ int   g_deg[NN];
__device__ int   g_rowptr[NN + 1];
__device__ int   g_cursor[NN];
__device__ int   g_csr_src[NE];
__device__ int   g_csr_type[NE];
__device__ float g_csr_w[NE];
__device__ float g_logmean;

// ---------------- helpers ----------------
__device__ __forceinline__ float f2tf32(float x) {
    unsigned u;
    asm("cvt.rna.tf32.f32 %0, %1;" : "=r"(u) : "f"(x));
    return __uint_as_float(u);
}

__device__ __forceinline__ void mma_tf32(float c[4], const float a[4], const float b[2]) {
    asm volatile(
        "mma.sync.aligned.m16n8k8.row.col.f32.tf32.tf32.f32 "
        "{%0,%1,%2,%3}, {%4,%5,%6,%7}, {%8,%9}, {%0,%1,%2,%3};"
        : "+f"(c[0]), "+f"(c[1]), "+f"(c[2]), "+f"(c[3])
        : "r"(__float_as_uint(a[0])), "r"(__float_as_uint(a[1])),
          "r"(__float_as_uint(a[2])), "r"(__float_as_uint(a[3])),
          "r"(__float_as_uint(b[0])), "r"(__float_as_uint(b[1])));
}

__device__ __forceinline__ void acc_edge(float4 xv, float4 rv, float w,
                                         float4& s, float4& q, float4& mx, float4& mn) {
    float m;
    m = xv.x * rv.x * w; s.x += m; q.x += m * m; mx.x = fmaxf(mx.x, m); mn.x = fminf(mn.x, m);
    m = xv.y * rv.y * w; s.y += m; q.y += m * m; mx.y = fmaxf(mx.y, m); mn.y = fminf(mn.y, m);
    m = xv.z * rv.z * w; s.z += m; q.z += m * m; mx.z = fmaxf(mx.z, m); mn.z = fminf(mn.z, m);
    m = xv.w * rv.w * w; s.w += m; q.w += m * m; mx.w = fmaxf(mx.w, m); mn.w = fminf(mn.w, m);
}

// ---------------- setup kernels ----------------
__global__ void k_zero_deg() {
    int i = blockIdx.x * blockDim.x + threadIdx.x;
    if (i < NN) g_deg[i] = 0;
}

__global__ void k_count(const int* __restrict__ ei) {
    int e = blockIdx.x * blockDim.x + threadIdx.x;
    if (e < NE) atomicAdd(&g_deg[ei[NE + e]], 1);
}

// single-block exclusive scan of deg -> rowptr/cursor; also mean of log(deg+1)
__global__ void k_scan() {
    __shared__ int wsum[32];
    __shared__ int srun;
    __shared__ float fw[32];
    int tid = threadIdx.x, lane = tid & 31, wid = tid >> 5;
    if (tid == 0) srun = 0;
    float logacc = 0.f;
    for (int base = 0; base < NN; base += 1024) {
        __syncthreads();
        int run = srun;
        int i = base + tid;
        int v = (i < NN) ? g_deg[i] : 0;
        if (i < NN) logacc += logf((float)v + 1.0f);
        int xin = v;
        #pragma unroll
        for (int off = 1; off < 32; off <<= 1) {
            int y = __shfl_up_sync(FULL, xin, off);
            if (lane >= off) xin += y;
        }
        if (lane == 31) wsum[wid] = xin;
        __syncthreads();
        if (wid == 0) {
            int w = wsum[lane];
            #pragma unroll
            for (int off = 1; off < 32; off <<= 1) {
                int y = __shfl_up_sync(FULL, w, off);
                if (lane >= off) w += y;
            }
            wsum[lane] = w;
        }
        __syncthreads();
        int woff = wid ? wsum[wid - 1] : 0;
        int excl = run + woff + xin - v;
        if (i < NN) { g_rowptr[i] = excl; g_cursor[i] = excl; }
        if (tid == 0) srun = run + wsum[31];
    }
    __syncthreads();
    if (tid == 0) g_rowptr[NN] = srun;
    #pragma unroll
    for (int off = 16; off; off >>= 1) logacc += __shfl_xor_sync(FULL, logacc, off);
    if (lane == 0) fw[wid] = logacc;
    __syncthreads();
    if (tid == 0) {
        float t = 0.f;
        for (int i = 0; i < 32; i++) t += fw[i];
        g_logmean = t / (float)NN;
    }
}

__global__ void k_scatter(const int* __restrict__ ei, const int* __restrict__ et,
                          const float* __restrict__ ew) {
    int e = blockIdx.x * blockDim.x + threadIdx.x;
    if (e < NE) {
        int d = ei[NE + e];
        int pos = atomicAdd(&g_cursor[d], 1);
        g_csr_src[pos]  = ei[e];
        g_csr_type[pos] = et[e];
        g_csr_w[pos]    = ew[e];
    }
}

__global__ void k_scales() {
    int i = blockIdx.x * blockDim.x + threadIdx.x;
    if (i < NN) {
        float sc = logf((float)g_deg[i] + 1.0f) / g_logmean;
        g_scales[3 * i + 0] = 1.0f;
        g_scales[3 * i + 1] = sc;
        g_scales[3 * i + 2] = 1.0f / fmaxf(sc, 1e-2f);
    }
}

__global__ void k_copyx(const float* __restrict__ x0) {
    int i = blockIdx.x * blockDim.x + threadIdx.x;  // exactly NN*32 float4
    ((float4*)g_x)[i] = ((const float4*)x0)[i];
}

// ---------------- per-layer aggregation: one warp per dst node ----------------
__global__ void k_agg(const float* __restrict__ relw, const float* __restrict__ x0) {
    int gw = (blockIdx.x * blockDim.x + threadIdx.x) >> 5;
    int lane = threadIdx.x & 31;
    if (gw >= NN) return;
    const float4* X  = (const float4*)g_x;
    const float4* X0 = (const float4*)x0;
    const float4* RW = (const float4*)relw;
    float4 b = X0[gw * 32 + lane];     // boundary self-message = x0
    float4 s = b;
    float4 q = make_float4(b.x * b.x, b.y * b.y, b.z * b.z, b.w * b.w);
    float4 mx = b, mn = b;
    int e0 = g_rowptr[gw], e1 = g_rowptr[gw + 1];
    int e = e0;
    for (; e + 1 < e1; e += 2) {
        int s0 = g_csr_src[e],     t0 = g_csr_type[e];     float w0 = g_csr_w[e];
        int s1 = g_csr_src[e + 1], t1 = g_csr_type[e + 1]; float w1 = g_csr_w[e + 1];
        float4 xa = X[s0 * 32 + lane], ra = RW[t0 * 32 + lane];
        float4 xb = X[s1 * 32 + lane], rb = RW[t1 * 32 + lane];
        acc_edge(xa, ra, w0, s, q, mx, mn);
        acc_edge(xb, rb, w1, s, q, mx, mn);
    }
    if (e < e1) {
        int s0 = g_csr_src[e], t0 = g_csr_type[e]; float w0 = g_csr_w[e];
        float4 xa = X[s0 * 32 + lane], ra = RW[t0 * 32 + lane];
        acc_edge(xa, ra, w0, s, q, mx, mn);
    }
    float inv = 1.0f / ((float)(e1 - e0) + 1.0f);
    float4 mean = make_float4(s.x * inv, s.y * inv, s.z * inv, s.w * inv);
    float4 sqm  = make_float4(q.x * inv, q.y * inv, q.z * inv, q.w * inv);
    float4 sd;
    sd.x = sqrtf(fmaxf(sqm.x - mean.x * mean.x, 1e-6f));
    sd.y = sqrtf(fmaxf(sqm.y - mean.y * mean.y, 1e-6f));
    sd.z = sqrtf(fmaxf(sqm.z - mean.z * mean.z, 1e-6f));
    sd.w = sqrtf(fmaxf(sqm.w - mean.w * mean.w, 1e-6f));
    float4* F = (float4*)g_feats;
    size_t base = (size_t)gw * 128;   // 512 floats per node = 128 float4
    F[base + lane]      = mean;
    F[base + 32 + lane] = mx;
    F[base + 64 + lane] = mn;
    F[base + 96 + lane] = sd;
}

// ---------------- fused GEMM (tf32 mma) + bias + LayerNorm + ReLU + residual ----------------
// C[128 rows x 128 cols] per CTA.  A[n,k] is virtual:
//   k < 1536: feats[n][(k>>7)&3][k&127] * scales[n][k>>9];   k >= 1536: x[n][k-1536]
__global__ void __launch_bounds__(256) k_gemm(const float* __restrict__ W,
                                              const float* __restrict__ bias,
                                              const float* __restrict__ gamma,
                                              const float* __restrict__ beta) {
    __shared__ float As[128][36];    // pad 36: conflict-free frag loads
    __shared__ float Bs[32][136];    // pad 136: conflict-free frag loads
    __shared__ float red1[2][128];
    __shared__ float red2[2][128];
    __shared__ float sG[128], sBt[128], sBias[128];

    int tid = threadIdx.x;
    if (tid < 128) { sG[tid] = gamma[tid]; sBt[tid] = beta[tid]; sBias[tid] = bias[tid]; }
    int bm = blockIdx.x * 128;
    int warp = tid >> 5, lane = tid & 31, g = lane >> 2, t4 = lane & 3;
    int wm = warp >> 1, wn = warp & 1;

    float acc[2][8][4];
    #pragma unroll
    for (int mt = 0; mt < 2; mt++)
        #pragma unroll
        for (int nt = 0; nt < 8; nt++)
            #pragma unroll
            for (int c = 0; c < 4; c++) acc[mt][nt][c] = 0.f;

    int ar = tid >> 1, ah = tid & 1;        // A loader: 2 threads per row, 16 k each
    int gmRow = bm + ar;
    bool rok = gmRow < NN;
    int br = tid >> 3, bc = tid & 7;        // B loader: 8 threads per k-row

    for (int kt = 0; kt < 52; kt++) {
        int kb = kt * 32;
        { // load A tile (virtual A, scaled, tf32-rounded)
            int k0 = kb + ah * 16;
            if (rok) {
                const float* src; float sc;
                if (k0 < 1536) {
                    int s = k0 >> 9, f = (k0 >> 7) & 3, d0 = k0 & 127;
                    src = g_feats + (size_t)gmRow * 512 + f * 128 + d0;
                    sc = g_scales[gmRow * 3 + s];
                } else {
                    src = g_x + (size_t)gmRow * 128 + (k0 - 1536);
                    sc = 1.0f;
                }
                #pragma unroll
                for (int q = 0; q < 4; q++) {
                    float4 v = ((const float4*)src)[q];
                    int kl = ah * 16 + q * 4;
                    As[ar][kl + 0] = f2tf32(v.x * sc);
                    As[ar][kl + 1] = f2tf32(v.y * sc);
                    As[ar][kl + 2] = f2tf32(v.z * sc);
                    As[ar][kl + 3] = f2tf32(v.w * sc);
                }
            } else {
                #pragma unroll
                for (int q = 0; q < 4; q++) {
                    int kl = ah * 16 + q * 4;
                    As[ar][kl] = As[ar][kl + 1] = As[ar][kl + 2] = As[ar][kl + 3] = 0.f;
                }
            }
        }
        { // load B tile (weights)
            const float* wsrc = W + (size_t)(kb + br) * 128;
            #pragma unroll
            for (int q = 0; q < 4; q++) {
                int col = bc * 4 + q * 32;
                float4 v = *(const float4*)(wsrc + col);
                Bs[br][col + 0] = f2tf32(v.x);
                Bs[br][col + 1] = f2tf32(v.y);
                Bs[br][col + 2] = f2tf32(v.z);
                Bs[br][col + 3] = f2tf32(v.w);
            }
        }
        __syncthreads();
        #pragma unroll
        for (int ks = 0; ks < 4; ks++) {
            int kk = ks * 8;
            float a[2][4], b[8][2];
            #pragma unroll
            for (int mt = 0; mt < 2; mt++) {
                int r0 = wm * 32 + mt * 16;
                a[mt][0] = As[r0 + g][kk + t4];
                a[mt][1] = As[r0 + g + 8][kk + t4];
                a[mt][2] = As[r0 + g][kk + t4 + 4];
                a[mt][3] = As[r0 + g + 8][kk + t4 + 4];
            }
            #pragma unroll
            for (int nt = 0; nt < 8; nt++) {
                int c0 = wn * 64 + nt * 8 + g;
                b[nt][0] = Bs[kk + t4][c0];
                b[nt][1] = Bs[kk + t4 + 4][c0];
            }
            #pragma unroll
            for (int mt = 0; mt < 2; mt++)
                #pragma unroll
                for (int nt = 0; nt < 8; nt++)
                    mma_tf32(acc[mt][nt], a[mt], b[nt]);
        }
        __syncthreads();
    }

    // ---- epilogue: +bias, LayerNorm over 128 cols, ReLU, residual, in-place x ----
    #pragma unroll
    for (int mt = 0; mt < 2; mt++)
        #pragma unroll
        for (int nt = 0; nt < 8; nt++)
            #pragma unroll
            for (int c = 0; c < 4; c++) {
                int col = wn * 64 + nt * 8 + 2 * t4 + (c & 1);
                acc[mt][nt][c] += sBias[col];
            }
    #pragma unroll
    for (int mt = 0; mt < 2; mt++)
        #pragma unroll
        for (int h = 0; h < 2; h++) {
            float S1 = 0.f, S2 = 0.f;
            #pragma unroll
            for (int nt = 0; nt < 8; nt++) {
                float v0 = acc[mt][nt][2 * h], v1 = acc[mt][nt][2 * h + 1];
                S1 += v0 + v1; S2 += v0 * v0 + v1 * v1;
            }
            S1 += __shfl_xor_sync(FULL, S1, 1); S2 += __shfl_xor_sync(FULL, S2, 1);
            S1 += __shfl_xor_sync(FULL, S1, 2); S2 += __shfl_xor_sync(FULL, S2, 2);
            if (t4 == 0) {
                int rl = wm * 32 + mt * 16 + h * 8 + g;
                red1[wn][rl] = S1; red2[wn][rl] = S2;
            }
        }
    __syncthreads();
    #pragma unroll
    for (int mt = 0; mt < 2; mt++)
        #pragma unroll
        for (int h = 0; h < 2; h++) {
            int rl = wm * 32 + mt * 16 + h * 8 + g;
            int grow = bm + rl;
            float S1 = red1[0][rl] + red1[1][rl];
            float S2 = red2[0][rl] + red2[1][rl];
            float mean = S1 * (1.0f / 128.0f);
            float var  = S2 * (1.0f / 128.0f) - mean * mean;
            float rstd = rsqrtf(var + 1e-5f);
            if (grow < NN) {
                #pragma unroll
                for (int nt = 0; nt < 8; nt++)
                    #pragma unroll
                    for (int c = 0; c < 2; c++) {
                        int col = wn * 64 + nt * 8 + 2 * t4 + c;
                        float v = (acc[mt][nt][2 * h + c] - mean) * rstd * sG[col] + sBt[col];
                        v = fmaxf(v, 0.0f);
                        g_x[(size_t)grow * 128 + col] = v + g_x[(size_t)grow * 128 + col];
                    }
            }
        }
}

// ---------------- distmult scoring: one warp per (b,k) triple ----------------
__global__ void k_score(const float* __restrict__ qw, const int* __restrict__ src,
                        const int* __restrict__ rel, const int* __restrict__ dst,
                        float* __restrict__ out) {
    int gw = (blockIdx.x * blockDim.x + threadIdx.x) >> 5;
    int lane = threadIdx.x & 31;
    if (gw >= BQ * KQ) return;
    int si = src[gw], ri = rel[gw], di = dst[gw];
    const float4* X = (const float4*)g_x;
    const float4* Q = (const float4*)qw;
    float4 a = X[si * 32 + lane], q = Q[ri * 32 + lane], b = X[di * 32 + lane];
    float v = a.x * q.x * b.x + a.y * q.y * b.y + a.z * q.z * b.z + a.w * q.w * b.w;
    #pragma unroll
    for (int off = 16; off; off >>= 1) v += __shfl_xor_sync(FULL, v, off);
    if (lane == 0) out[gw] = v;
}

// ---------------- launch ----------------
extern "C" void kernel_launch(void* const* d_in, const int* in_sizes, int n_in,
                              void* d_out, int out_size) {
    const float* x0     = (const float*)d_in[0];
    const int*   ei     = (const int*)d_in[1];
    const int*   etype  = (const int*)d_in[2];
    const float* ew     = (const float*)d_in[3];
    const float* rel_w  = (const float*)d_in[4];
    const float* lin_w  = (const float*)d_in[5];
    const float* lin_b  = (const float*)d_in[6];
    const float* ln_g   = (const float*)d_in[7];
    const float* ln_b   = (const float*)d_in[8];
    const float* qw     = (const float*)d_in[9];
    const int*   src    = (const int*)d_in[10];
    const int*   rel    = (const int*)d_in[11];
    const int*   dst    = (const int*)d_in[12];
    float* out = (float*)d_out;

    k_zero_deg<<<(NN + 255) / 256, 256>>>();
    k_count<<<(NE + 255) / 256, 256>>>(ei);
    k_scan<<<1, 1024>>>();
    k_scatter<<<(NE + 255) / 256, 256>>>(ei, etype, ew);
    k_scales<<<(NN + 255) / 256, 256>>>();
    k_copyx<<<(NN * 32) / 256, 256>>>(x0);

    for (int l = 0; l < 4; l++) {
        k_agg<<<NN / 8, 256>>>(rel_w + (size_t)l * NRL * D, x0);
        k_gemm<<<(NN + 127) / 128, 256>>>(lin_w + (size_t)l * KD * D,
                                          lin_b + (size_t)l * D,
                                          ln_g + (size_t)l * D,
                                          ln_b + (size_t)l * D);
    }
    k_score<<<(BQ * KQ) / 8, 256>>>(qw, src, rel, dst, out);
}

// round 2
// speedup vs baseline: 1.0834x; 1.0834x over previous
#include <cuda_runtime.h>
#include <cstdint>
#include <math.h>

#define FULL 0xffffffffu

static const int NN  = 50000;
static const int NE  = 500000;
static const int D   = 128;
static const int NRL = 51;
static const int KD  = 1664;   // 13*128
static const int BQ  = 1024;
static const int KQ  = 32;

// ---------------- scratch (device globals; no runtime allocation) ----------------
__device__ float g_x[NN * D];            // current node features (25.6 MB)
__device__ float g_feats[NN * 4 * D];    // [N][4][128] mean,max,min,std (102.4 MB)
__device__ float g_scales[NN * 3];       // PNA scalers per node
__device__ int   g_deg[NN];
__device__ int   g_rowptr[NN + 1];
__device__ int   g_cursor[NN];
__device__ int   g_csr_src[NE];
__device__ int   g_csr_type[NE];
__device__ float g_csr_w[NE];
__device__ float g_logmean;

// ---------------- helpers ----------------
__device__ __forceinline__ float f2tf32(float x) {
    unsigned u;
    asm("cvt.rna.tf32.f32 %0, %1;" : "=r"(u) : "f"(x));
    return __uint_as_float(u);
}

__device__ __forceinline__ void mma_tf32(float c[4], const float a[4], const float b[2]) {
    asm volatile(
        "mma.sync.aligned.m16n8k8.row.col.f32.tf32.tf32.f32 "
        "{%0,%1,%2,%3}, {%4,%5,%6,%7}, {%8,%9}, {%0,%1,%2,%3};"
        : "+f"(c[0]), "+f"(c[1]), "+f"(c[2]), "+f"(c[3])
        : "r"(__float_as_uint(a[0])), "r"(__float_as_uint(a[1])),
          "r"(__float_as_uint(a[2])), "r"(__float_as_uint(a[3])),
          "r"(__float_as_uint(b[0])), "r"(__float_as_uint(b[1])));
}

__device__ __forceinline__ void cp16(float* smem_dst, const float* gsrc, int sz) {
    uint32_t s = (uint32_t)__cvta_generic_to_shared(smem_dst);
    asm volatile("cp.async.cg.shared.global [%0], [%1], 16, %2;"
                 :: "r"(s), "l"(gsrc), "r"(sz));
}
#define CP_COMMIT() asm volatile("cp.async.commit_group;")
#define CP_WAIT(n)  asm volatile("cp.async.wait_group %0;" :: "n"(n))

__device__ __forceinline__ void acc_edge(float4 xv, float4 rv, float w,
                                         float4& s, float4& q, float4& mx, float4& mn) {
    float m;
    m = xv.x * rv.x * w; s.x += m; q.x += m * m; mx.x = fmaxf(mx.x, m); mn.x = fminf(mn.x, m);
    m = xv.y * rv.y * w; s.y += m; q.y += m * m; mx.y = fmaxf(mx.y, m); mn.y = fminf(mn.y, m);
    m = xv.z * rv.z * w; s.z += m; q.z += m * m; mx.z = fmaxf(mx.z, m); mn.z = fminf(mn.z, m);
    m = xv.w * rv.w * w; s.w += m; q.w += m * m; mx.w = fmaxf(mx.w, m); mn.w = fminf(mn.w, m);
}

// ---------------- setup kernels ----------------
__global__ void k_zero_deg() {
    int i = blockIdx.x * blockDim.x + threadIdx.x;
    if (i < NN) g_deg[i] = 0;
}

__global__ void k_count(const int* __restrict__ ei) {
    int e = blockIdx.x * blockDim.x + threadIdx.x;
    if (e < NE) atomicAdd(&g_deg[ei[NE + e]], 1);
}

// single-block exclusive scan of deg -> rowptr/cursor; also mean of log(deg+1)
__global__ void k_scan() {
    __shared__ int wsum[32];
    __shared__ int srun;
    __shared__ float fw[32];
    int tid = threadIdx.x, lane = tid & 31, wid = tid >> 5;
    if (tid == 0) srun = 0;
    float logacc = 0.f;
    for (int base = 0; base < NN; base += 1024) {
        __syncthreads();
        int run = srun;
        int i = base + tid;
        int v = (i < NN) ? g_deg[i] : 0;
        if (i < NN) logacc += logf((float)v + 1.0f);
        int xin = v;
        #pragma unroll
        for (int off = 1; off < 32; off <<= 1) {
            int y = __shfl_up_sync(FULL, xin, off);
            if (lane >= off) xin += y;
        }
        if (lane == 31) wsum[wid] = xin;
        __syncthreads();
        if (wid == 0) {
            int w = wsum[lane];
            #pragma unroll
            for (int off = 1; off < 32; off <<= 1) {
                int y = __shfl_up_sync(FULL, w, off);
                if (lane >= off) w += y;
            }
            wsum[lane] = w;
        }
        __syncthreads();
        int woff = wid ? wsum[wid - 1] : 0;
        int excl = run + woff + xin - v;
        if (i < NN) { g_rowptr[i] = excl; g_cursor[i] = excl; }
        if (tid == 0) srun = run + wsum[31];
    }
    __syncthreads();
    if (tid == 0) g_rowptr[NN] = srun;
    #pragma unroll
    for (int off = 16; off; off >>= 1) logacc += __shfl_xor_sync(FULL, logacc, off);
    if (lane == 0) fw[wid] = logacc;
    __syncthreads();
    if (tid == 0) {
        float t = 0.f;
        for (int i = 0; i < 32; i++) t += fw[i];
        g_logmean = t / (float)NN;
    }
}

__global__ void k_scatter(const int* __restrict__ ei, const int* __restrict__ et,
                          const float* __restrict__ ew) {
    int e = blockIdx.x * blockDim.x + threadIdx.x;
    if (e < NE) {
        int d = ei[NE + e];
        int pos = atomicAdd(&g_cursor[d], 1);
        g_csr_src[pos]  = ei[e];
        g_csr_type[pos] = et[e];
        g_csr_w[pos]    = ew[e];
    }
}

__global__ void k_scales() {
    int i = blockIdx.x * blockDim.x + threadIdx.x;
    if (i < NN) {
        float sc = logf((float)g_deg[i] + 1.0f) / g_logmean;
        g_scales[3 * i + 0] = 1.0f;
        g_scales[3 * i + 1] = sc;
        g_scales[3 * i + 2] = 1.0f / fmaxf(sc, 1e-2f);
    }
}

__global__ void k_copyx(const float* __restrict__ x0) {
    int i = blockIdx.x * blockDim.x + threadIdx.x;  // exactly NN*32 float4
    ((float4*)g_x)[i] = ((const float4*)x0)[i];
}

// ---------------- per-layer aggregation: one warp per dst node ----------------
__global__ void k_agg(const float* __restrict__ relw, const float* __restrict__ x0) {
    int gw = (blockIdx.x * blockDim.x + threadIdx.x) >> 5;
    int lane = threadIdx.x & 31;
    if (gw >= NN) return;
    const float4* X  = (const float4*)g_x;
    const float4* X0 = (const float4*)x0;
    const float4* RW = (const float4*)relw;
    float4 b = X0[gw * 32 + lane];     // boundary self-message = x0
    float4 s = b;
    float4 q = make_float4(b.x * b.x, b.y * b.y, b.z * b.z, b.w * b.w);
    float4 mx = b, mn = b;
    int e0 = g_rowptr[gw], e1 = g_rowptr[gw + 1];
    int e = e0;
    for (; e + 3 < e1; e += 4) {
        int s0 = g_csr_src[e],     t0 = g_csr_type[e];     float w0 = g_csr_w[e];
        int s1 = g_csr_src[e + 1], t1 = g_csr_type[e + 1]; float w1 = g_csr_w[e + 1];
        int s2 = g_csr_src[e + 2], t2 = g_csr_type[e + 2]; float w2 = g_csr_w[e + 2];
        int s3 = g_csr_src[e + 3], t3 = g_csr_type[e + 3]; float w3 = g_csr_w[e + 3];
        float4 xa = X[s0 * 32 + lane], ra = RW[t0 * 32 + lane];
        float4 xb = X[s1 * 32 + lane], rb = RW[t1 * 32 + lane];
        float4 xc = X[s2 * 32 + lane], rc = RW[t2 * 32 + lane];
        float4 xd = X[s3 * 32 + lane], rd = RW[t3 * 32 + lane];
        acc_edge(xa, ra, w0, s, q, mx, mn);
        acc_edge(xb, rb, w1, s, q, mx, mn);
        acc_edge(xc, rc, w2, s, q, mx, mn);
        acc_edge(xd, rd, w3, s, q, mx, mn);
    }
    for (; e < e1; e++) {
        int s0 = g_csr_src[e], t0 = g_csr_type[e]; float w0 = g_csr_w[e];
        float4 xa = X[s0 * 32 + lane], ra = RW[t0 * 32 + lane];
        acc_edge(xa, ra, w0, s, q, mx, mn);
    }
    float inv = 1.0f / ((float)(e1 - e0) + 1.0f);
    float4 mean = make_float4(s.x * inv, s.y * inv, s.z * inv, s.w * inv);
    float4 sqm  = make_float4(q.x * inv, q.y * inv, q.z * inv, q.w * inv);
    float4 sd;
    sd.x = sqrtf(fmaxf(sqm.x - mean.x * mean.x, 1e-6f));
    sd.y = sqrtf(fmaxf(sqm.y - mean.y * mean.y, 1e-6f));
    sd.z = sqrtf(fmaxf(sqm.z - mean.z * mean.z, 1e-6f));
    sd.w = sqrtf(fmaxf(sqm.w - mean.w * mean.w, 1e-6f));
    float4* F = (float4*)g_feats;
    size_t base = (size_t)gw * 128;   // 512 floats per node = 128 float4
    F[base + lane]      = mean;
    F[base + 32 + lane] = mx;
    F[base + 64 + lane] = mn;
    F[base + 96 + lane] = sd;
}

// ---------------- fused GEMM (tf32 mma, cp.async double-buffered) ----------------
// + bias + LayerNorm + ReLU + residual.  C tile = 128 rows x 128 cols per CTA.
// Virtual A[n,k]: k<1536 -> feats[n][k mod 512] * scales[n][k>>9]; k>=1536 -> x[n][k-1536]
// Scaling + tf32 rounding applied at fragment-load time (raw f32 streamed via cp.async).
static const int SA = 36;                 // As row stride (floats), conflict-free + 16B aligned
static const int SB = 136;                // Bs row stride
static const int A_STG = 128 * SA;        // 4608
static const int B_STG = 32 * SB;         // 4352
static const int OFF_B    = 2 * A_STG;            // 9216
static const int OFF_SC   = OFF_B + 2 * B_STG;    // 17920
static const int OFF_G    = OFF_SC + 512;         // 18432
static const int OFF_BT   = OFF_G + 128;          // 18560
static const int OFF_BIAS = OFF_BT + 128;         // 18688
static const int OFF_R1   = OFF_BIAS + 128;       // 18816
static const int OFF_R2   = OFF_R1 + 256;         // 19072
static const int SMEM_FLOATS = OFF_R2 + 256;      // 19328 -> 77312 bytes

__global__ void __launch_bounds__(256, 2) k_gemm(const float* __restrict__ W,
                                                 const float* __restrict__ bias,
                                                 const float* __restrict__ gamma,
                                                 const float* __restrict__ beta) {
    extern __shared__ float sm[];
    float* sA    = sm;
    float* sB    = sm + OFF_B;
    float* sSc   = sm + OFF_SC;
    float* sG    = sm + OFF_G;
    float* sBt   = sm + OFF_BT;
    float* sBias = sm + OFF_BIAS;
    float* red1  = sm + OFF_R1;
    float* red2  = sm + OFF_R2;

    int tid = threadIdx.x;
    int bm = blockIdx.x * 128;
    if (tid < 128) { sG[tid] = gamma[tid]; sBt[tid] = beta[tid]; sBias[tid] = bias[tid]; }
    for (int i = tid; i < 512; i += 256) {
        int s = i >> 7, n = i & 127;
        float v = 1.0f;
        if (s < 3 && bm + n < NN) v = g_scales[(bm + n) * 3 + s];
        sSc[i] = v;
    }

    int warp = tid >> 5, lane = tid & 31, g = lane >> 2, t4 = lane & 3;
    int wm = warp >> 1, wn = warp & 1;

    // loader indexing
    int ar = tid >> 1, ah = tid & 1;     // A: 2 threads per row, 16 floats each
    int gmRow = bm + ar;
    bool rok = gmRow < NN;
    int rClamp = rok ? gmRow : (NN - 1);

    float acc[2][8][4];
    #pragma unroll
    for (int mt = 0; mt < 2; mt++)
        #pragma unroll
        for (int nt = 0; nt < 8; nt++)
            #pragma unroll
            for (int c = 0; c < 4; c++) acc[mt][nt][c] = 0.f;

    // tile loaders (raw f32, zero-fill OOB rows)
    auto loadA = [&](int kt) {
        int kb = kt * 32;
        int k0 = kb + ah * 16;
        const float* src;
        if (k0 < 1536) src = g_feats + (size_t)rClamp * 512 + (k0 & 511);
        else           src = g_x + (size_t)rClamp * 128 + (k0 - 1536);
        float* dst = sA + (kt & 1) * A_STG + ar * SA + ah * 16;
        int sz = rok ? 16 : 0;
        #pragma unroll
        for (int q = 0; q < 4; q++) cp16(dst + q * 4, src + q * 4, sz);
    };
    auto loadB = [&](int kt) {
        int kb = kt * 32;
        float* dstb = sB + (kt & 1) * B_STG;
        #pragma unroll
        for (int q = 0; q < 4; q++) {
            int c = tid + q * 256;
            int row = c >> 5, col = (c & 31) * 4;
            cp16(dstb + row * SB + col, W + (size_t)(kb + row) * 128 + col, 16);
        }
    };

    loadA(0); loadB(0); CP_COMMIT();
    loadA(1); loadB(1); CP_COMMIT();

    for (int kt = 0; kt < 52; kt++) {
        if (kt < 51) { CP_WAIT(1); } else { CP_WAIT(0); }
        __syncthreads();
        const float* As_ = sA + (kt & 1) * A_STG;
        const float* Bs_ = sB + (kt & 1) * B_STG;
        int sseg = (kt < 48) ? (kt >> 4) : 3;

        float scv[2][2];
        #pragma unroll
        for (int mt = 0; mt < 2; mt++) {
            int r0 = wm * 32 + mt * 16 + g;
            scv[mt][0] = sSc[sseg * 128 + r0];
            scv[mt][1] = sSc[sseg * 128 + r0 + 8];
        }
        #pragma unroll
        for (int ks = 0; ks < 4; ks++) {
            int kk = ks * 8;
            float a[2][4], b[8][2];
            #pragma unroll
            for (int mt = 0; mt < 2; mt++) {
                int r0 = wm * 32 + mt * 16 + g;
                a[mt][0] = f2tf32(As_[(r0)     * SA + kk + t4]     * scv[mt][0]);
                a[mt][1] = f2tf32(As_[(r0 + 8) * SA + kk + t4]     * scv[mt][1]);
                a[mt][2] = f2tf32(As_[(r0)     * SA + kk + t4 + 4] * scv[mt][0]);
                a[mt][3] = f2tf32(As_[(r0 + 8) * SA + kk + t4 + 4] * scv[mt][1]);
            }
            #pragma unroll
            for (int nt = 0; nt < 8; nt++) {
                int c0 = wn * 64 + nt * 8 + g;
                b[nt][0] = f2tf32(Bs_[(kk + t4)     * SB + c0]);
                b[nt][1] = f2tf32(Bs_[(kk + t4 + 4) * SB + c0]);
            }
            #pragma unroll
            for (int mt = 0; mt < 2; mt++)
                #pragma unroll
                for (int nt = 0; nt < 8; nt++)
                    mma_tf32(acc[mt][nt], a[mt], b[nt]);
        }
        __syncthreads();
        if (kt + 2 < 52) { loadA(kt + 2); loadB(kt + 2); CP_COMMIT(); }
    }

    // ---- epilogue: +bias, LayerNorm over 128 cols, ReLU, residual, in-place x ----
    #pragma unroll
    for (int mt = 0; mt < 2; mt++)
        #pragma unroll
        for (int nt = 0; nt < 8; nt++)
            #pragma unroll
            for (int c = 0; c < 4; c++) {
                int col = wn * 64 + nt * 8 + 2 * t4 + (c & 1);
                acc[mt][nt][c] += sBias[col];
            }
    #pragma unroll
    for (int mt = 0; mt < 2; mt++)
        #pragma unroll
        for (int h = 0; h < 2; h++) {
            float S1 = 0.f, S2 = 0.f;
            #pragma unroll
            for (int nt = 0; nt < 8; nt++) {
                float v0 = acc[mt][nt][2 * h], v1 = acc[mt][nt][2 * h + 1];
                S1 += v0 + v1; S2 += v0 * v0 + v1 * v1;
            }
            S1 += __shfl_xor_sync(FULL, S1, 1); S2 += __shfl_xor_sync(FULL, S2, 1);
            S1 += __shfl_xor_sync(FULL, S1, 2); S2 += __shfl_xor_sync(FULL, S2, 2);
            if (t4 == 0) {
                int rl = wm * 32 + mt * 16 + h * 8 + g;
                red1[wn * 128 + rl] = S1; red2[wn * 128 + rl] = S2;
            }
        }
    __syncthreads();
    #pragma unroll
    for (int mt = 0; mt < 2; mt++)
        #pragma unroll
        for (int h = 0; h < 2; h++) {
            int rl = wm * 32 + mt * 16 + h * 8 + g;
            int grow = bm + rl;
            float S1 = red1[rl] + red1[128 + rl];
            float S2 = red2[rl] + red2[128 + rl];
            float mean = S1 * (1.0f / 128.0f);
            float var  = S2 * (1.0f / 128.0f) - mean * mean;
            float rstd = rsqrtf(var + 1e-5f);
            if (grow < NN) {
                #pragma unroll
                for (int nt = 0; nt < 8; nt++)
                    #pragma unroll
                    for (int c = 0; c < 2; c++) {
                        int col = wn * 64 + nt * 8 + 2 * t4 + c;
                        float v = (acc[mt][nt][2 * h + c] - mean) * rstd * sG[col] + sBt[col];
                        v = fmaxf(v, 0.0f);
                        g_x[(size_t)grow * 128 + col] = v + g_x[(size_t)grow * 128 + col];
                    }
            }
        }
}

// ---------------- distmult scoring: one warp per (b,k) triple ----------------
__global__ void k_score(const float* __restrict__ qw, const int* __restrict__ src,
                        const int* __restrict__ rel, const int* __restrict__ dst,
                        float* __restrict__ out) {
    int gw = (blockIdx.x * blockDim.x + threadIdx.x) >> 5;
    int lane = threadIdx.x & 31;
    if (gw >= BQ * KQ) return;
    int si = src[gw], ri = rel[gw], di = dst[gw];
    const float4* X = (const float4*)g_x;
    const float4* Q = (const float4*)qw;
    float4 a = X[si * 32 + lane], q = Q[ri * 32 + lane], b = X[di * 32 + lane];
    float v = a.x * q.x * b.x + a.y * q.y * b.y + a.z * q.z * b.z + a.w * q.w * b.w;
    #pragma unroll
    for (int off = 16; off; off >>= 1) v += __shfl_xor_sync(FULL, v, off);
    if (lane == 0) out[gw] = v;
}

// ---------------- launch ----------------
extern "C" void kernel_launch(void* const* d_in, const int* in_sizes, int n_in,
                              void* d_out, int out_size) {
    const float* x0     = (const float*)d_in[0];
    const int*   ei     = (const int*)d_in[1];
    const int*   etype  = (const int*)d_in[2];
    const float* ew     = (const float*)d_in[3];
    const float* rel_w  = (const float*)d_in[4];
    const float* lin_w  = (const float*)d_in[5];
    const float* lin_b  = (const float*)d_in[6];
    const float* ln_g   = (const float*)d_in[7];
    const float* ln_b   = (const float*)d_in[8];
    const float* qw     = (const float*)d_in[9];
    const int*   src    = (const int*)d_in[10];
    const int*   rel    = (const int*)d_in[11];
    const int*   dst    = (const int*)d_in[12];
    float* out = (float*)d_out;

    cudaFuncSetAttribute(k_gemm, cudaFuncAttributeMaxDynamicSharedMemorySize,
                         SMEM_FLOATS * (int)sizeof(float));

    k_zero_deg<<<(NN + 255) / 256, 256>>>();
    k_count<<<(NE + 255) / 256, 256>>>(ei);
    k_scan<<<1, 1024>>>();
    k_scatter<<<(NE + 255) / 256, 256>>>(ei, etype, ew);
    k_scales<<<(NN + 255) / 256, 256>>>();
    k_copyx<<<(NN * 32) / 256, 256>>>(x0);

    for (int l = 0; l < 4; l++) {
        k_agg<<<NN / 8, 256>>>(rel_w + (size_t)l * NRL * D, x0);
        k_gemm<<<(NN + 127) / 128, 256, SMEM_FLOATS * (int)sizeof(float)>>>(
            lin_w + (size_t)l * KD * D,
            lin_b + (size_t)l * D,
            ln_g + (size_t)l * D,
            ln_b + (size_t)l * D);
    }
    k_score<<<(BQ * KQ) / 8, 256>>>(qw, src, rel, dst, out);
}

// round 5
// speedup vs baseline: 1.7308x; 1.5976x over previous
#include <cuda_runtime.h>
#include <cuda_fp16.h>
#include <cstdint>
#include <math.h>

#define FULL 0xffffffffu

static const int NN  = 50000;
static const int NE  = 500000;
static const int D   = 128;
static const int NRL = 51;
static const int KD  = 1664;   // 13*128
static const int BQ  = 1024;
static const int KQ  = 32;
static const int WN  = 212992; // 1664*128 per layer

// ---------------- scratch (device globals; no runtime allocation) ----------------
__device__ float  g_x[NN * D];            // f32 node features (agg gather + score)
__device__ __half g_featsP[NN * 1536];    // pre-scaled 12*D feats, fp16, k-permuted
__device__ __half g_xp[NN * D];           // fp16 k-permuted shadow of x
__device__ __half g_Wt[4 * WN];           // transposed+permuted weights [l][n][k] fp16
__device__ int    g_deg[NN];
__device__ int    g_rowptr[NN + 1];
__device__ int    g_cursor[NN];
__device__ int    g_csr_src[NE];
__device__ int    g_csr_type[NE];
__device__ float  g_csr_w[NE];
__device__ float  g_logmean;

// ---------------- helpers ----------------
__device__ __forceinline__ void cp16z(void* smem_dst, const void* gsrc, int sz) {
    uint32_t s = (uint32_t)__cvta_generic_to_shared(smem_dst);
    asm volatile("cp.async.cg.shared.global [%0], [%1], 16, %2;"
                 :: "r"(s), "l"(gsrc), "r"(sz));
}
#define CP_COMMIT() asm volatile("cp.async.commit_group;")
#define CP_WAIT(n)  asm volatile("cp.async.wait_group %0;" :: "n"(n))

#define LDS128(r, addr) \
    asm volatile("ld.shared.v4.b32 {%0,%1,%2,%3}, [%4];" \
                 : "=r"((r)[0]), "=r"((r)[1]), "=r"((r)[2]), "=r"((r)[3]) \
                 : "r"(addr))

__device__ __forceinline__ void mma_f16(float c[4], uint32_t a0, uint32_t a1,
                                        uint32_t a2, uint32_t a3,
                                        uint32_t b0, uint32_t b1) {
    asm volatile(
        "mma.sync.aligned.m16n8k16.row.col.f32.f16.f16.f32 "
        "{%0,%1,%2,%3}, {%4,%5,%6,%7}, {%8,%9}, {%0,%1,%2,%3};"
        : "+f"(c[0]), "+f"(c[1]), "+f"(c[2]), "+f"(c[3])
        : "r"(a0), "r"(a1), "r"(a2), "r"(a3), "r"(b0), "r"(b1));
}

__device__ __forceinline__ void acc_edge(float4 xv, float4 rv, float w,
                                         float4& s, float4& q, float4& mx, float4& mn) {
    float m;
    m = xv.x * rv.x * w; s.x += m; q.x += m * m; mx.x = fmaxf(mx.x, m); mn.x = fminf(mn.x, m);
    m = xv.y * rv.y * w; s.y += m; q.y += m * m; mx.y = fmaxf(mx.y, m); mn.y = fminf(mn.y, m);
    m = xv.z * rv.z * w; s.z += m; q.z += m * m; mx.z = fmaxf(mx.z, m); mn.z = fminf(mn.z, m);
    m = xv.w * rv.w * w; s.w += m; q.w += m * m; mx.w = fmaxf(mx.w, m); mn.w = fminf(mn.w, m);
}

// ---------------- setup kernels ----------------
// weights: [l][k][n] f32 -> g_Wt [l][n][kchunk][perm32] fp16; also zero deg
__global__ void k_transW(const float* __restrict__ W) {
    int idx = blockIdx.x * blockDim.x + threadIdx.x;
    if (idx < NN) g_deg[idx] = 0;
    if (idx < 4 * WN) {
        int l = idx / WN, r = idx - l * WN;
        int n = r / KD, kk = r - n * KD;
        int base = kk & ~31, p = kk & 31;
        int lsrc = 2 * (p >> 3) + 8 * ((p & 7) >> 1) + (p & 1);  // inverse perm
        g_Wt[idx] = __float2half_rn(W[(size_t)l * WN + (size_t)(base + lsrc) * 128 + n]);
    }
}

__global__ void k_count(const int* __restrict__ ei) {
    int e = blockIdx.x * blockDim.x + threadIdx.x;
    if (e < NE) atomicAdd(&g_deg[ei[NE + e]], 1);
}

__global__ void k_scan() {
    __shared__ int wsum[32];
    __shared__ int srun;
    __shared__ float fw[32];
    int tid = threadIdx.x, lane = tid & 31, wid = tid >> 5;
    if (tid == 0) srun = 0;
    float logacc = 0.f;
    for (int base = 0; base < NN; base += 1024) {
        __syncthreads();
        int run = srun;
        int i = base + tid;
        int v = (i < NN) ? g_deg[i] : 0;
        if (i < NN) logacc += logf((float)v + 1.0f);
        int xin = v;
        #pragma unroll
        for (int off = 1; off < 32; off <<= 1) {
            int y = __shfl_up_sync(FULL, xin, off);
            if (lane >= off) xin += y;
        }
        if (lane == 31) wsum[wid] = xin;
        __syncthreads();
        if (wid == 0) {
            int w = wsum[lane];
            #pragma unroll
            for (int off = 1; off < 32; off <<= 1) {
                int y = __shfl_up_sync(FULL, w, off);
                if (lane >= off) w += y;
            }
            wsum[lane] = w;
        }
        __syncthreads();
        int woff = wid ? wsum[wid - 1] : 0;
        int excl = run + woff + xin - v;
        if (i < NN) { g_rowptr[i] = excl; g_cursor[i] = excl; }
        if (tid == 0) srun = run + wsum[31];
    }
    __syncthreads();
    if (tid == 0) g_rowptr[NN] = srun;
    #pragma unroll
    for (int off = 16; off; off >>= 1) logacc += __shfl_xor_sync(FULL, logacc, off);
    if (lane == 0) fw[wid] = logacc;
    __syncthreads();
    if (tid == 0) {
        float t = 0.f;
        for (int i = 0; i < 32; i++) t += fw[i];
        g_logmean = t / (float)NN;
    }
}

__global__ void k_scatter(const int* __restrict__ ei, const int* __restrict__ et,
                          const float* __restrict__ ew) {
    int e = blockIdx.x * blockDim.x + threadIdx.x;
    if (e < NE) {
        int d = ei[NE + e];
        int pos = atomicAdd(&g_cursor[d], 1);
        g_csr_src[pos]  = ei[e];
        g_csr_type[pos] = et[e];
        g_csr_w[pos]    = ew[e];
    }
}

// x0 -> g_xp fp16 permuted
__global__ void k_permx0(const float* __restrict__ x0) {
    int idx = blockIdx.x * blockDim.x + threadIdx.x;  // NN*32
    int node = idx >> 5, m32 = idx & 31;
    float4 v = ((const float4*)x0)[(size_t)node * 32 + m32];
    int chunk = m32 >> 3, m = m32 & 7;
    int p0 = 16 * (m & 1) + 2 * (m >> 1);
    __half2* dst = (__half2*)(g_xp + (size_t)node * 128 + chunk * 32);
    dst[p0 >> 1]       = __floats2half2_rn(v.x, v.y);
    dst[(p0 >> 1) + 4] = __floats2half2_rn(v.z, v.w);
}

// ---------------- per-layer aggregation: one warp per dst node ----------------
// writes g_featsP: 12 chunks = [s][f] pre-scaled, fp16, k-permuted
__global__ void k_agg(const float* __restrict__ relw, const float* __restrict__ x0,
                      const float* __restrict__ xin) {
    int gw = (blockIdx.x * blockDim.x + threadIdx.x) >> 5;
    int lane = threadIdx.x & 31;
    if (gw >= NN) return;
    const float4* X  = (const float4*)xin;
    const float4* X0 = (const float4*)x0;
    const float4* RW = (const float4*)relw;
    float4 b = X0[(size_t)gw * 32 + lane];
    float4 s = b;
    float4 q = make_float4(b.x * b.x, b.y * b.y, b.z * b.z, b.w * b.w);
    float4 mx = b, mn = b;
    int e0 = g_rowptr[gw], e1 = g_rowptr[gw + 1];
    int e = e0;
    for (; e + 3 < e1; e += 4) {
        int s0 = g_csr_src[e],     t0 = g_csr_type[e];     float w0 = g_csr_w[e];
        int s1 = g_csr_src[e + 1], t1 = g_csr_type[e + 1]; float w1 = g_csr_w[e + 1];
        int s2 = g_csr_src[e + 2], t2 = g_csr_type[e + 2]; float w2 = g_csr_w[e + 2];
        int s3 = g_csr_src[e + 3], t3 = g_csr_type[e + 3]; float w3 = g_csr_w[e + 3];
        float4 xa = X[s0 * 32 + lane], ra = RW[t0 * 32 + lane];
        float4 xb = X[s1 * 32 + lane], rb = RW[t1 * 32 + lane];
        float4 xc = X[s2 * 32 + lane], rc = RW[t2 * 32 + lane];
        float4 xd = X[s3 * 32 + lane], rd = RW[t3 * 32 + lane];
        acc_edge(xa, ra, w0, s, q, mx, mn);
        acc_edge(xb, rb, w1, s, q, mx, mn);
        acc_edge(xc, rc, w2, s, q, mx, mn);
        acc_edge(xd, rd, w3, s, q, mx, mn);
    }
    for (; e < e1; e++) {
        int s0 = g_csr_src[e], t0 = g_csr_type[e]; float w0 = g_csr_w[e];
        float4 xa = X[s0 * 32 + lane], ra = RW[t0 * 32 + lane];
        acc_edge(xa, ra, w0, s, q, mx, mn);
    }
    int degn = e1 - e0;
    float inv = 1.0f / ((float)degn + 1.0f);
    float4 mean = make_float4(s.x * inv, s.y * inv, s.z * inv, s.w * inv);
    float4 sqm  = make_float4(q.x * inv, q.y * inv, q.z * inv, q.w * inv);
    float4 sd;
    sd.x = sqrtf(fmaxf(sqm.x - mean.x * mean.x, 1e-6f));
    sd.y = sqrtf(fmaxf(sqm.y - mean.y * mean.y, 1e-6f));
    sd.z = sqrtf(fmaxf(sqm.z - mean.z * mean.z, 1e-6f));
    sd.w = sqrtf(fmaxf(sqm.w - mean.w * mean.w, 1e-6f));

    float lg = logf((float)degn + 1.0f) / g_logmean;
    float scv[3] = {1.0f, lg, 1.0f / fmaxf(lg, 1e-2f)};
    float4 feats[4] = {mean, mx, mn, sd};

    int m = lane & 7, crow = lane >> 3;
    int p0h = (16 * (m & 1) + 2 * (m >> 1)) >> 1;    // half2 index of first pair
    __half* basep = g_featsP + (size_t)gw * 1536;
    #pragma unroll
    for (int ss = 0; ss < 3; ss++) {
        float sc = scv[ss];
        #pragma unroll
        for (int f = 0; f < 4; f++) {
            float4 v = feats[f];
            int chunk = ss * 16 + f * 4 + crow;
            __half2* dst = (__half2*)(basep + chunk * 32);
            dst[p0h]     = __floats2half2_rn(v.x * sc, v.y * sc);
            dst[p0h + 4] = __floats2half2_rn(v.z * sc, v.w * sc);
        }
    }
}

// ---------------- fp16 mma GEMM + bias + LN + ReLU + residual ----------------
// CTA tile 128x128, 8 warps (wm 0..3 x wn 0..1), warp tile 32x64.
// A/B fp16, 64B-per-row smem tiles, 4-stage cp.async ring.
static const int STG_B   = 8192;                 // one stage: 128 rows x 64B
static const int OFF_BST = 4 * STG_B;            // 32768: B stages
static const int OFF_BIAS = 8 * STG_B;           // 65536
static const int OFF_G    = OFF_BIAS + 512;
static const int OFF_BT   = OFF_G + 512;
static const int OFF_R1   = OFF_BT + 512;        // 256 f32
static const int OFF_R2   = OFF_R1 + 1024;
static const int SMEM_BYTES = OFF_R2 + 1024;     // 69120

__global__ void __launch_bounds__(256, 2) k_gemm(const __half* __restrict__ Wt,
                                                 const float* __restrict__ bias,
                                                 const float* __restrict__ gamma,
                                                 const float* __restrict__ beta,
                                                 const float* __restrict__ xin,
                                                 int write_xp) {
    extern __shared__ __align__(128) char smc[];
    uint32_t sbase = (uint32_t)__cvta_generic_to_shared(smc);
    int tid = threadIdx.x, wid = tid >> 5, lane = tid & 31;
    int g = lane >> 2, t4 = lane & 3;
    int wm = wid >> 1, wn = wid & 1;
    int bm = blockIdx.x * 128;

    float* sBias = (float*)(smc + OFF_BIAS);
    float* sG    = (float*)(smc + OFF_G);
    float* sBt   = (float*)(smc + OFF_BT);
    float* red1  = (float*)(smc + OFF_R1);
    float* red2  = (float*)(smc + OFF_R2);
    if (tid < 128) { sBias[tid] = bias[tid]; sG[tid] = gamma[tid]; sBt[tid] = beta[tid]; }

    float acc[2][8][4];
    #pragma unroll
    for (int mt = 0; mt < 2; mt++)
        #pragma unroll
        for (int nt = 0; nt < 8; nt++)
            #pragma unroll
            for (int c = 0; c < 4; c++) acc[mt][nt][c] = 0.f;

    auto issueA = [&](int kt) {
        char* dst = smc + (kt & 3) * STG_B;
        #pragma unroll
        for (int qq = 0; qq < 2; qq++) {
            int c = tid + qq * 256;
            int row = c >> 2, cc = c & 3;
            int gr = bm + row;
            bool ok = gr < NN;
            int rn = ok ? gr : 0;
            const char* src;
            if (kt < 48) src = (const char*)(g_featsP + (size_t)rn * 1536) + kt * 64 + cc * 16;
            else         src = (const char*)(g_xp + (size_t)rn * 128) + (kt - 48) * 64 + cc * 16;
            cp16z(dst + c * 16, src, ok ? 16 : 0);
        }
    };
    auto issueB = [&](int kt) {
        char* dst = smc + OFF_BST + (kt & 3) * STG_B;
        #pragma unroll
        for (int qq = 0; qq < 2; qq++) {
            int c = tid + qq * 256;
            int n = c >> 2, cc = c & 3;
            const char* src = (const char*)(Wt + (size_t)n * KD) + kt * 64 + cc * 16;
            cp16z(dst + c * 16, src, 16);
        }
    };

    issueA(0); issueB(0); CP_COMMIT();
    issueA(1); issueB(1); CP_COMMIT();
    issueA(2); issueB(2); CP_COMMIT();

    for (int kt = 0; kt < 52; kt++) {
        if (kt <= 49)      { CP_WAIT(2); }
        else if (kt == 50) { CP_WAIT(1); }
        else               { CP_WAIT(0); }
        __syncthreads();
        if (kt + 3 < 52) { issueA(kt + 3); issueB(kt + 3); CP_COMMIT(); }

        uint32_t Au = sbase + (kt & 3) * STG_B;
        uint32_t Bu = sbase + OFF_BST + (kt & 3) * STG_B;
        uint32_t raf[2][2][4];
        #pragma unroll
        for (int mt = 0; mt < 2; mt++)
            #pragma unroll
            for (int rh = 0; rh < 2; rh++) {
                int row = wm * 32 + mt * 16 + rh * 8 + g;
                LDS128(raf[mt][rh], Au + row * 64 + t4 * 16);
            }
        #pragma unroll
        for (int nt = 0; nt < 8; nt++) {
            uint32_t bb[4];
            int c0 = wn * 64 + nt * 8 + g;
            LDS128(bb, Bu + c0 * 64 + t4 * 16);
            #pragma unroll
            for (int mt = 0; mt < 2; mt++) {
                mma_f16(acc[mt][nt], raf[mt][0][0], raf[mt][1][0],
                        raf[mt][0][1], raf[mt][1][1], bb[0], bb[1]);
                mma_f16(acc[mt][nt], raf[mt][0][2], raf[mt][1][2],
                        raf[mt][0][3], raf[mt][1][3], bb[2], bb[3]);
            }
        }
    }
    __syncthreads();

    // ---- epilogue: +bias, LayerNorm(128), ReLU, residual; write g_x + g_xp ----
    #pragma unroll
    for (int mt = 0; mt < 2; mt++)
        #pragma unroll
        for (int nt = 0; nt < 8; nt++)
            #pragma unroll
            for (int c = 0; c < 4; c++) {
                int col = wn * 64 + nt * 8 + 2 * t4 + (c & 1);
                acc[mt][nt][c] += sBias[col];
            }
    #pragma unroll
    for (int mt = 0; mt < 2; mt++)
        #pragma unroll
        for (int h = 0; h < 2; h++) {
            float S1 = 0.f, S2 = 0.f;
            #pragma unroll
            for (int nt = 0; nt < 8; nt++) {
                float v0 = acc[mt][nt][2 * h], v1 = acc[mt][nt][2 * h + 1];
                S1 += v0 + v1; S2 += v0 * v0 + v1 * v1;
            }
            S1 += __shfl_xor_sync(FULL, S1, 1); S2 += __shfl_xor_sync(FULL, S2, 1);
            S1 += __shfl_xor_sync(FULL, S1, 2); S2 += __shfl_xor_sync(FULL, S2, 2);
            if (t4 == 0) {
                int rl = wm * 32 + mt * 16 + h * 8 + g;
                red1[wn * 128 + rl] = S1; red2[wn * 128 + rl] = S2;
            }
        }
    __syncthreads();
    #pragma unroll
    for (int mt = 0; mt < 2; mt++)
        #pragma unroll
        for (int h = 0; h < 2; h++) {
            int rl = wm * 32 + mt * 16 + h * 8 + g;
            int grow = bm + rl;
            float T1 = red1[rl] + red1[128 + rl];
            float T2 = red2[rl] + red2[128 + rl];
            float mean = T1 * (1.0f / 128.0f);
            float var  = T2 * (1.0f / 128.0f) - mean * mean;
            float rstd = rsqrtf(var + 1e-5f);
            if (grow < NN) {
                #pragma unroll
                for (int nt = 0; nt < 8; nt++) {
                    int col = wn * 64 + nt * 8 + 2 * t4;
                    float v0 = (acc[mt][nt][2 * h] - mean) * rstd * sG[col] + sBt[col];
                    float v1 = (acc[mt][nt][2 * h + 1] - mean) * rstd * sG[col + 1] + sBt[col + 1];
                    v0 = fmaxf(v0, 0.f); v1 = fmaxf(v1, 0.f);
                    float2 xv = *(const float2*)(xin + (size_t)grow * 128 + col);
                    v0 += xv.x; v1 += xv.y;
                    *(float2*)(g_x + (size_t)grow * 128 + col) = make_float2(v0, v1);
                    if (write_xp) {
                        int chunk = wn * 2 + (nt >> 2);
                        int pb = t4 * 8 + (nt & 3) * 2;
                        ((__half2*)(g_xp + (size_t)grow * 128 + chunk * 32))[pb >> 1] =
                            __floats2half2_rn(v0, v1);
                    }
                }
            }
        }
}

// ---------------- distmult scoring ----------------
__global__ void k_score(const float* __restrict__ qw, const int* __restrict__ src,
                        const int* __restrict__ rel, const int* __restrict__ dst,
                        float* __restrict__ out) {
    int gw = (blockIdx.x * blockDim.x + threadIdx.x) >> 5;
    int lane = threadIdx.x & 31;
    if (gw >= BQ * KQ) return;
    int si = src[gw], ri = rel[gw], di = dst[gw];
    const float4* X = (const float4*)g_x;
    const float4* Q = (const float4*)qw;
    float4 a = X[(size_t)si * 32 + lane], q = Q[ri * 32 + lane], b = X[(size_t)di * 32 + lane];
    float v = a.x * q.x * b.x + a.y * q.y * b.y + a.z * q.z * b.z + a.w * q.w * b.w;
    #pragma unroll
    for (int off = 16; off; off >>= 1) v += __shfl_xor_sync(FULL, v, off);
    if (lane == 0) out[gw] = v;
}

// ---------------- launch ----------------
extern "C" void kernel_launch(void* const* d_in, const int* in_sizes, int n_in,
                              void* d_out, int out_size) {
    const float* x0     = (const float*)d_in[0];
    const int*   ei     = (const int*)d_in[1];
    const int*   etype  = (const int*)d_in[2];
    const float* ew     = (const float*)d_in[3];
    const float* rel_w  = (const float*)d_in[4];
    const float* lin_w  = (const float*)d_in[5];
    const float* lin_b  = (const float*)d_in[6];
    const float* ln_g   = (const float*)d_in[7];
    const float* ln_b   = (const float*)d_in[8];
    const float* qw     = (const float*)d_in[9];
    const int*   src    = (const int*)d_in[10];
    const int*   rel    = (const int*)d_in[11];
    const int*   dst    = (const int*)d_in[12];
    float* out = (float*)d_out;

    cudaFuncSetAttribute(k_gemm, cudaFuncAttributeMaxDynamicSharedMemorySize, SMEM_BYTES);

    __half* wt_dev = nullptr;
    float*  gx_dev = nullptr;
    cudaGetSymbolAddress((void**)&wt_dev, g_Wt);
    cudaGetSymbolAddress((void**)&gx_dev, g_x);

    k_transW<<<(4 * WN + 255) / 256, 256>>>(lin_w);
    k_count<<<(NE + 255) / 256, 256>>>(ei);
    k_scan<<<1, 1024>>>();
    k_scatter<<<(NE + 255) / 256, 256>>>(ei, etype, ew);
    k_permx0<<<(NN * 32) / 256, 256>>>(x0);

    for (int l = 0; l < 4; l++) {
        const float* xin = (l == 0) ? x0 : gx_dev;
        k_agg<<<NN / 8, 256>>>(rel_w + (size_t)l * NRL * D, x0, xin);
        k_gemm<<<(NN + 127) / 128, 256, SMEM_BYTES>>>(
            wt_dev + (size_t)l * WN,
            lin_b + (size_t)l * D,
            ln_g + (size_t)l * D,
            ln_b + (size_t)l * D,
            xin,
            (l < 3) ? 1 : 0);
    }
    k_score<<<(BQ * KQ) / 8, 256>>>(qw, src, rel, dst, out);
}

// round 14
// speedup vs baseline: 1.7882x; 1.0332x over previous
#include <cuda_runtime.h>
#include <cuda_fp16.h>
#include <cstdint>
#include <math.h>

#define FULL 0xffffffffu

static const int NN  = 50000;
static const int NE  = 500000;
static const int D   = 128;
static const int NRL = 51;
static const int KD  = 1664;   // 13*128
static const int BQ  = 1024;
static const int KQ  = 32;
static const int WN  = 212992; // 1664*128 per layer

// ---------------- scratch (device globals; no runtime allocation) ----------------
__device__ float  g_x[NN * D];            // f32 node features (residual + score)
__device__ __half g_featsP[NN * 1536];    // pre-scaled 12*D feats, fp16, k-permuted
__device__ __half g_xp[NN * D];           // fp16 k-permuted shadow of x (agg gather + GEMM A)
__device__ __half g_x0p[NN * D];          // fp16 k-permuted x0 (boundary message)
__device__ float  g_relP[4 * NRL * D];    // k-permuted rel_w (f32)
__device__ __half g_Wt[4 * WN];           // transposed+permuted weights [l][n][k] fp16
__device__ int    g_deg[NN];
__device__ int    g_rowptr[NN + 1];
__device__ int    g_cursor[NN];
__device__ int    g_csr_src[NE];
__device__ int    g_csr_type[NE];
__device__ float  g_csr_w[NE];
__device__ float  g_logmean;

// ---------------- helpers ----------------
__device__ __forceinline__ void cp16z(void* smem_dst, const void* gsrc, int sz) {
    uint32_t s = (uint32_t)__cvta_generic_to_shared(smem_dst);
    asm volatile("cp.async.cg.shared.global [%0], [%1], 16, %2;"
                 :: "r"(s), "l"(gsrc), "r"(sz));
}
#define CP_COMMIT() asm volatile("cp.async.commit_group;")
#define CP_WAIT(n)  asm volatile("cp.async.wait_group %0;" :: "n"(n))

#define LDS128(r, addr) \
    asm volatile("ld.shared.v4.b32 {%0,%1,%2,%3}, [%4];" \
                 : "=r"((r)[0]), "=r"((r)[1]), "=r"((r)[2]), "=r"((r)[3]) \
                 : "r"(addr))

__device__ __forceinline__ void mma_f16(float c[4], uint32_t a0, uint32_t a1,
                                        uint32_t a2, uint32_t a3,
                                        uint32_t b0, uint32_t b1) {
    asm volatile(
        "mma.sync.aligned.m16n8k16.row.col.f32.f16.f16.f32 "
        "{%0,%1,%2,%3}, {%4,%5,%6,%7}, {%8,%9}, {%0,%1,%2,%3};"
        : "+f"(c[0]), "+f"(c[1]), "+f"(c[2]), "+f"(c[3])
        : "r"(a0), "r"(a1), "r"(a2), "r"(a3), "r"(b0), "r"(b1));
}

__device__ __forceinline__ void acc_edge(float4 xv, float4 rv, float w,
                                         float4& s, float4& q, float4& mx, float4& mn) {
    float m;
    m = xv.x * rv.x * w; s.x += m; q.x += m * m; mx.x = fmaxf(mx.x, m); mn.x = fminf(mn.x, m);
    m = xv.y * rv.y * w; s.y += m; q.y += m * m; mx.y = fmaxf(mx.y, m); mn.y = fminf(mn.y, m);
    m = xv.z * rv.z * w; s.z += m; q.z += m * m; mx.z = fmaxf(mx.z, m); mn.z = fminf(mn.z, m);
    m = xv.w * rv.w * w; s.w += m; q.w += m * m; mx.w = fmaxf(mx.w, m); mn.w = fminf(mn.w, m);
}

__device__ __forceinline__ float4 h4_to_f4(uint2 u) {
    float2 a = __half22float2(*(__half2*)&u.x);
    float2 b = __half22float2(*(__half2*)&u.y);
    return make_float4(a.x, a.y, b.x, b.y);
}

// ---------------- setup kernels ----------------
// weights [l][k][n] f32 -> g_Wt [l][n][kchunk][perm32] fp16; rel_w -> g_relP; zero deg
__global__ void k_transW(const float* __restrict__ W, const float* __restrict__ relw) {
    int idx = blockIdx.x * blockDim.x + threadIdx.x;
    if (idx < NN) g_deg[idx] = 0;
    if (idx < 4 * NRL * 128) {
        int pos = idx & 127, tt = idx >> 7;
        int p = pos & 31, c = pos >> 5;
        int lsrc = 2 * (p >> 3) + 8 * ((p & 7) >> 1) + (p & 1);
        g_relP[idx] = relw[tt * 128 + c * 32 + lsrc];
    }
    if (idx < 4 * WN) {
        int l = idx / WN, r = idx - l * WN;
        int n = r / KD, kk = r - n * KD;
        int base = kk & ~31, p = kk & 31;
        int lsrc = 2 * (p >> 3) + 8 * ((p & 7) >> 1) + (p & 1);  // inverse perm
        g_Wt[idx] = __float2half_rn(W[(size_t)l * WN + (size_t)(base + lsrc) * 128 + n]);
    }
}

__global__ void k_count(const int* __restrict__ ei) {
    int e = blockIdx.x * blockDim.x + threadIdx.x;
    if (e < NE) atomicAdd(&g_deg[ei[NE + e]], 1);
}

__global__ void k_scan() {
    __shared__ int wsum[32];
    __shared__ int srun;
    __shared__ float fw[32];
    int tid = threadIdx.x, lane = tid & 31, wid = tid >> 5;
    if (tid == 0) srun = 0;
    float logacc = 0.f;
    for (int base = 0; base < NN; base += 1024) {
        __syncthreads();
        int run = srun;
        int i = base + tid;
        int v = (i < NN) ? g_deg[i] : 0;
        if (i < NN) logacc += logf((float)v + 1.0f);
        int xin = v;
        #pragma unroll
        for (int off = 1; off < 32; off <<= 1) {
            int y = __shfl_up_sync(FULL, xin, off);
            if (lane >= off) xin += y;
        }
        if (lane == 31) wsum[wid] = xin;
        __syncthreads();
        if (wid == 0) {
            int w = wsum[lane];
            #pragma unroll
            for (int off = 1; off < 32; off <<= 1) {
                int y = __shfl_up_sync(FULL, w, off);
                if (lane >= off) w += y;
            }
            wsum[lane] = w;
        }
        __syncthreads();
        int woff = wid ? wsum[wid - 1] : 0;
        int excl = run + woff + xin - v;
        if (i < NN) { g_rowptr[i] = excl; g_cursor[i] = excl; }
        if (tid == 0) srun = run + wsum[31];
    }
    __syncthreads();
    if (tid == 0) g_rowptr[NN] = srun;
    #pragma unroll
    for (int off = 16; off; off >>= 1) logacc += __shfl_xor_sync(FULL, logacc, off);
    if (lane == 0) fw[wid] = logacc;
    __syncthreads();
    if (tid == 0) {
        float t = 0.f;
        for (int i = 0; i < 32; i++) t += fw[i];
        g_logmean = t / (float)NN;
    }
}

__global__ void k_scatter(const int* __restrict__ ei, const int* __restrict__ et,
                          const float* __restrict__ ew) {
    int e = blockIdx.x * blockDim.x + threadIdx.x;
    if (e < NE) {
        int d = ei[NE + e];
        int pos = atomicAdd(&g_cursor[d], 1);
        g_csr_src[pos]  = ei[e];
        g_csr_type[pos] = et[e];
        g_csr_w[pos]    = ew[e];
    }
}

// x0 -> g_xp + g_x0p (fp16, k-permuted)
__global__ void k_permx0(const float* __restrict__ x0) {
    int idx = blockIdx.x * blockDim.x + threadIdx.x;  // NN*32
    int node = idx >> 5, m32 = idx & 31;
    float4 v = ((const float4*)x0)[(size_t)node * 32 + m32];
    int chunk = m32 >> 3, m = m32 & 7;
    int p0 = 16 * (m & 1) + 2 * (m >> 1);
    __half2 lo = __floats2half2_rn(v.x, v.y);
    __half2 hi = __floats2half2_rn(v.z, v.w);
    __half2* dst  = (__half2*)(g_xp + (size_t)node * 128 + chunk * 32);
    __half2* dst0 = (__half2*)(g_x0p + (size_t)node * 128 + chunk * 32);
    dst[p0 >> 1]        = lo;  dst[(p0 >> 1) + 4]  = hi;
    dst0[p0 >> 1]       = lo;  dst0[(p0 >> 1) + 4] = hi;
}

// ---------------- per-layer aggregation: one warp per dst node ----------------
// gathers permuted fp16 x (g_xp) + permuted rel_w; writes g_featsP (permuted fp16)
__global__ void k_agg(const float* __restrict__ relP) {
    int gw = (blockIdx.x * blockDim.x + threadIdx.x) >> 5;
    int lane = threadIdx.x & 31;
    if (gw >= NN) return;
    int off = lane * 4;   // 4 permuted dims per lane

    float4 b = h4_to_f4(*(const uint2*)(g_x0p + (size_t)gw * 128 + off));
    float4 s = b;
    float4 q = make_float4(b.x * b.x, b.y * b.y, b.z * b.z, b.w * b.w);
    float4 mx = b, mn = b;
    int e0 = g_rowptr[gw], e1 = g_rowptr[gw + 1];
    int e = e0;
    for (; e + 3 < e1; e += 4) {
        int s0 = g_csr_src[e],     t0 = g_csr_type[e];     float w0 = g_csr_w[e];
        int s1 = g_csr_src[e + 1], t1 = g_csr_type[e + 1]; float w1 = g_csr_w[e + 1];
        int s2 = g_csr_src[e + 2], t2 = g_csr_type[e + 2]; float w2 = g_csr_w[e + 2];
        int s3 = g_csr_src[e + 3], t3 = g_csr_type[e + 3]; float w3 = g_csr_w[e + 3];
        uint2 ua = *(const uint2*)(g_xp + (size_t)s0 * 128 + off);
        uint2 ub = *(const uint2*)(g_xp + (size_t)s1 * 128 + off);
        uint2 uc = *(const uint2*)(g_xp + (size_t)s2 * 128 + off);
        uint2 ud = *(const uint2*)(g_xp + (size_t)s3 * 128 + off);
        float4 ra = *(const float4*)(relP + t0 * 128 + off);
        float4 rb = *(const float4*)(relP + t1 * 128 + off);
        float4 rc = *(const float4*)(relP + t2 * 128 + off);
        float4 rd = *(const float4*)(relP + t3 * 128 + off);
        acc_edge(h4_to_f4(ua), ra, w0, s, q, mx, mn);
        acc_edge(h4_to_f4(ub), rb, w1, s, q, mx, mn);
        acc_edge(h4_to_f4(uc), rc, w2, s, q, mx, mn);
        acc_edge(h4_to_f4(ud), rd, w3, s, q, mx, mn);
    }
    for (; e < e1; e++) {
        int s0 = g_csr_src[e], t0 = g_csr_type[e]; float w0 = g_csr_w[e];
        uint2 ua = *(const uint2*)(g_xp + (size_t)s0 * 128 + off);
        float4 ra = *(const float4*)(relP + t0 * 128 + off);
        acc_edge(h4_to_f4(ua), ra, w0, s, q, mx, mn);
    }
    int degn = e1 - e0;
    float inv = 1.0f / ((float)degn + 1.0f);
    float4 mean = make_float4(s.x * inv, s.y * inv, s.z * inv, s.w * inv);
    float4 sqm  = make_float4(q.x * inv, q.y * inv, q.z * inv, q.w * inv);
    float4 sd;
    sd.x = sqrtf(fmaxf(sqm.x - mean.x * mean.x, 1e-6f));
    sd.y = sqrtf(fmaxf(sqm.y - mean.y * mean.y, 1e-6f));
    sd.z = sqrtf(fmaxf(sqm.z - mean.z * mean.z, 1e-6f));
    sd.w = sqrtf(fmaxf(sqm.w - mean.w * mean.w, 1e-6f));

    float lg = logf((float)degn + 1.0f) / g_logmean;
    float scv[3] = {1.0f, lg, 1.0f / fmaxf(lg, 1e-2f)};
    float4 feats[4] = {mean, mx, mn, sd};

    int cl = lane >> 3, wo = (lane & 7) * 4;     // chunk row + within-chunk offset
    __half* basep = g_featsP + (size_t)gw * 1536;
    #pragma unroll
    for (int ss = 0; ss < 3; ss++) {
        float sc = scv[ss];
        #pragma unroll
        for (int f = 0; f < 4; f++) {
            float4 v = feats[f];
            int chunk = ss * 16 + f * 4 + cl;
            __half2 lo = __floats2half2_rn(v.x * sc, v.y * sc);
            __half2 hi = __floats2half2_rn(v.z * sc, v.w * sc);
            uint2 pk;
            pk.x = *(uint32_t*)&lo; pk.y = *(uint32_t*)&hi;
            *(uint2*)(basep + chunk * 32 + wo) = pk;
        }
    }
}

// ---------------- fp16 mma GEMM + bias + LN + ReLU + residual ----------------
static const int STG_B   = 8192;                 // one stage: 128 rows x 64B
static const int OFF_BST = 4 * STG_B;            // 32768: B stages
static const int OFF_BIAS = 8 * STG_B;           // 65536
static const int OFF_G    = OFF_BIAS + 512;
static const int OFF_BT   = OFF_G + 512;
static const int OFF_R1   = OFF_BT + 512;        // 256 f32
static const int OFF_R2   = OFF_R1 + 1024;
static const int SMEM_BYTES = OFF_R2 + 1024;     // 69120

__global__ void __launch_bounds__(256, 2) k_gemm(const __half* __restrict__ Wt,
                                                 const float* __restrict__ bias,
                                                 const float* __restrict__ gamma,
                                                 const float* __restrict__ beta,
                                                 const float* __restrict__ xin,
                                                 int write_xp) {
    extern __shared__ __align__(128) char smc[];
    uint32_t sbase = (uint32_t)__cvta_generic_to_shared(smc);
    int tid = threadIdx.x, wid = tid >> 5, lane = tid & 31;
    int g = lane >> 2, t4 = lane & 3;
    int wm = wid >> 1, wn = wid & 1;
    int bm = blockIdx.x * 128;

    float* sBias = (float*)(smc + OFF_BIAS);
    float* sG    = (float*)(smc + OFF_G);
    float* sBt   = (float*)(smc + OFF_BT);
    float* red1  = (float*)(smc + OFF_R1);
    float* red2  = (float*)(smc + OFF_R2);
    if (tid < 128) { sBias[tid] = bias[tid]; sG[tid] = gamma[tid]; sBt[tid] = beta[tid]; }

    float acc[2][8][4];
    #pragma unroll
    for (int mt = 0; mt < 2; mt++)
        #pragma unroll
        for (int nt = 0; nt < 8; nt++)
            #pragma unroll
            for (int c = 0; c < 4; c++) acc[mt][nt][c] = 0.f;

    auto issueA = [&](int kt) {
        char* dst = smc + (kt & 3) * STG_B;
        #pragma unroll
        for (int qq = 0; qq < 2; qq++) {
            int c = tid + qq * 256;
            int row = c >> 2, cc = c & 3;
            int gr = bm + row;
            bool ok = gr < NN;
            int rn = ok ? gr : 0;
            const char* src;
            if (kt < 48) src = (const char*)(g_featsP + (size_t)rn * 1536) + kt * 64 + cc * 16;
            else         src = (const char*)(g_xp + (size_t)rn * 128) + (kt - 48) * 64 + cc * 16;
            cp16z(dst + c * 16, src, ok ? 16 : 0);
        }
    };
    auto issueB = [&](int kt) {
        char* dst = smc + OFF_BST + (kt & 3) * STG_B;
        #pragma unroll
        for (int qq = 0; qq < 2; qq++) {
            int c = tid + qq * 256;
            int n = c >> 2, cc = c & 3;
            const char* src = (const char*)(Wt + (size_t)n * KD) + kt * 64 + cc * 16;
            cp16z(dst + c * 16, src, 16);
        }
    };

    issueA(0); issueB(0); CP_COMMIT();
    issueA(1); issueB(1); CP_COMMIT();
    issueA(2); issueB(2); CP_COMMIT();

    for (int kt = 0; kt < 52; kt++) {
        if (kt <= 49)      { CP_WAIT(2); }
        else if (kt == 50) { CP_WAIT(1); }
        else               { CP_WAIT(0); }
        __syncthreads();
        if (kt + 3 < 52) { issueA(kt + 3); issueB(kt + 3); CP_COMMIT(); }

        uint32_t Au = sbase + (kt & 3) * STG_B;
        uint32_t Bu = sbase + OFF_BST + (kt & 3) * STG_B;
        uint32_t raf[2][2][4];
        #pragma unroll
        for (int mt = 0; mt < 2; mt++)
            #pragma unroll
            for (int rh = 0; rh < 2; rh++) {
                int row = wm * 32 + mt * 16 + rh * 8 + g;
                LDS128(raf[mt][rh], Au + row * 64 + t4 * 16);
            }
        #pragma unroll
        for (int nt = 0; nt < 8; nt++) {
            uint32_t bb[4];
            int c0 = wn * 64 + nt * 8 + g;
            LDS128(bb, Bu + c0 * 64 + t4 * 16);
            #pragma unroll
            for (int mt = 0; mt < 2; mt++) {
                mma_f16(acc[mt][nt], raf[mt][0][0], raf[mt][1][0],
                        raf[mt][0][1], raf[mt][1][1], bb[0], bb[1]);
                mma_f16(acc[mt][nt], raf[mt][0][2], raf[mt][1][2],
                        raf[mt][0][3], raf[mt][1][3], bb[2], bb[3]);
            }
        }
    }
    __syncthreads();

    // ---- epilogue: +bias, LayerNorm(128), ReLU, residual; write g_x + g_xp ----
    #pragma unroll
    for (int mt = 0; mt < 2; mt++)
        #pragma unroll
        for (int nt = 0; nt < 8; nt++)
            #pragma unroll
            for (int c = 0; c < 4; c++) {
                int col = wn * 64 + nt * 8 + 2 * t4 + (c & 1);
                acc[mt][nt][c] += sBias[col];
            }
    #pragma unroll
    for (int mt = 0; mt < 2; mt++)
        #pragma unroll
        for (int h = 0; h < 2; h++) {
            float S1 = 0.f, S2 = 0.f;
            #pragma unroll
            for (int nt = 0; nt < 8; nt++) {
                float v0 = acc[mt][nt][2 * h], v1 = acc[mt][nt][2 * h + 1];
                S1 += v0 + v1; S2 += v0 * v0 + v1 * v1;
            }
            S1 += __shfl_xor_sync(FULL, S1, 1); S2 += __shfl_xor_sync(FULL, S2, 1);
            S1 += __shfl_xor_sync(FULL, S1, 2); S2 += __shfl_xor_sync(FULL, S2, 2);
            if (t4 == 0) {
                int rl = wm * 32 + mt * 16 + h * 8 + g;
                red1[wn * 128 + rl] = S1; red2[wn * 128 + rl] = S2;
            }
        }
    __syncthreads();
    #pragma unroll
    for (int mt = 0; mt < 2; mt++)
        #pragma unroll
        for (int h = 0; h < 2; h++) {
            int rl = wm * 32 + mt * 16 + h * 8 + g;
            int grow = bm + rl;
            float T1 = red1[rl] + red1[128 + rl];
            float T2 = red2[rl] + red2[128 + rl];
            float mean = T1 * (1.0f / 128.0f);
            float var  = T2 * (1.0f / 128.0f) - mean * mean;
            float rstd = rsqrtf(var + 1e-5f);
            if (grow < NN) {
                #pragma unroll
                for (int nt = 0; nt < 8; nt++) {
                    int col = wn * 64 + nt * 8 + 2 * t4;
                    float v0 = (acc[mt][nt][2 * h] - mean) * rstd * sG[col] + sBt[col];
                    float v1 = (acc[mt][nt][2 * h + 1] - mean) * rstd * sG[col + 1] + sBt[col + 1];
                    v0 = fmaxf(v0, 0.f); v1 = fmaxf(v1, 0.f);
                    float2 xv = *(const float2*)(xin + (size_t)grow * 128 + col);
                    v0 += xv.x; v1 += xv.y;
                    *(float2*)(g_x + (size_t)grow * 128 + col) = make_float2(v0, v1);
                    if (write_xp) {
                        int chunk = wn * 2 + (nt >> 2);
                        int pb = t4 * 8 + (nt & 3) * 2;
                        ((__half2*)(g_xp + (size_t)grow * 128 + chunk * 32))[pb >> 1] =
                            __floats2half2_rn(v0, v1);
                    }
                }
            }
        }
}

// ---------------- distmult scoring ----------------
__global__ void k_score(const float* __restrict__ qw, const int* __restrict__ src,
                        const int* __restrict__ rel, const int* __restrict__ dst,
                        float* __restrict__ out) {
    int gw = (blockIdx.x * blockDim.x + threadIdx.x) >> 5;
    int lane = threadIdx.x & 31;
    if (gw >= BQ * KQ) return;
    int si = src[gw], ri = rel[gw], di = dst[gw];
    const float4* X = (const float4*)g_x;
    const float4* Q = (const float4*)qw;
    float4 a = X[(size_t)si * 32 + lane], q = Q[ri * 32 + lane], b = X[(size_t)di * 32 + lane];
    float v = a.x * q.x * b.x + a.y * q.y * b.y + a.z * q.z * b.z + a.w * q.w * b.w;
    #pragma unroll
    for (int off = 16; off; off >>= 1) v += __shfl_xor_sync(FULL, v, off);
    if (lane == 0) out[gw] = v;
}

// ---------------- launch ----------------
extern "C" void kernel_launch(void* const* d_in, const int* in_sizes, int n_in,
                              void* d_out, int out_size) {
    const float* x0     = (const float*)d_in[0];
    const int*   ei     = (const int*)d_in[1];
    const int*   etype  = (const int*)d_in[2];
    const float* ew     = (const float*)d_in[3];
    const float* rel_w  = (const float*)d_in[4];
    const float* lin_w  = (const float*)d_in[5];
    const float* lin_b  = (const float*)d_in[6];
    const float* ln_g   = (const float*)d_in[7];
    const float* ln_b   = (const float*)d_in[8];
    const float* qw     = (const float*)d_in[9];
    const int*   src    = (const int*)d_in[10];
    const int*   rel    = (const int*)d_in[11];
    const int*   dst    = (const int*)d_in[12];
    float* out = (float*)d_out;

    cudaFuncSetAttribute(k_gemm, cudaFuncAttributeMaxDynamicSharedMemorySize, SMEM_BYTES);

    __half* wt_dev = nullptr;
    float*  gx_dev = nullptr;
    float*  relp_dev = nullptr;
    cudaGetSymbolAddress((void**)&wt_dev, g_Wt);
    cudaGetSymbolAddress((void**)&gx_dev, g_x);
    cudaGetSymbolAddress((void**)&relp_dev, g_relP);

    k_transW<<<(4 * WN + 255) / 256, 256>>>(lin_w, rel_w);
    k_count<<<(NE + 255) / 256, 256>>>(ei);
    k_scan<<<1, 1024>>>();
    k_scatter<<<(NE + 255) / 256, 256>>>(ei, etype, ew);
    k_permx0<<<(NN * 32) / 256, 256>>>(x0);

    for (int l = 0; l < 4; l++) {
        const float* xin = (l == 0) ? x0 : gx_dev;
        k_agg<<<NN / 8, 256>>>(relp_dev + (size_t)l * NRL * 128);
        k_gemm<<<(NN + 127) / 128, 256, SMEM_BYTES>>>(
            wt_dev + (size_t)l * WN,
            lin_b + (size_t)l * D,
            ln_g + (size_t)l * D,
            ln_b + (size_t)l * D,
            xin,
            (l < 3) ? 1 : 0);
    }
    k_score<<<(BQ * KQ) / 8, 256>>>(qw, src, rel, dst, out);
}

// round 16
// speedup vs baseline: 1.8201x; 1.0178x over previous
#include <cuda_runtime.h>
#include <cuda_fp16.h>
#include <cstdint>
#include <math.h>

#define FULL 0xffffffffu

static const int NN  = 50000;
static const int NE  = 500000;
static const int D   = 128;
static const int NRL = 51;
static const int KD  = 1664;   // 13*128
static const int BQ  = 1024;
static const int KQ  = 32;
static const int WN  = 212992; // 1664*128 per layer

// ---------------- scratch (device globals; no runtime allocation) ----------------
__device__ float  g_x[NN * D];            // f32 node features (residual + score)
__device__ __half g_featsP[NN * 1536];    // pre-scaled 12*D feats, fp16, k-permuted
__device__ __half g_xp[NN * D];           // fp16 k-permuted shadow of x (agg gather + GEMM A)
__device__ __half g_x0p[NN * D];          // fp16 k-permuted x0 (boundary message)
__device__ float  g_relP[4 * NRL * D];    // k-permuted rel_w (f32)
__device__ __half g_Wt[4 * WN];           // transposed+permuted weights [l][n][k] fp16
__device__ int    g_deg[NN];              // zero at load; re-zeroed at end of k_score
__device__ int    g_rowptr[NN + 1];
__device__ int    g_cursor[NN];
__device__ int2   g_csr_st[NE];           // packed (src, type)
__device__ float  g_csr_w[NE];
__device__ float  g_logmean;

// ---------------- helpers ----------------
__device__ __forceinline__ void cp16z(void* smem_dst, const void* gsrc, int sz) {
    uint32_t s = (uint32_t)__cvta_generic_to_shared(smem_dst);
    asm volatile("cp.async.cg.shared.global [%0], [%1], 16, %2;"
                 :: "r"(s), "l"(gsrc), "r"(sz));
}
#define CP_COMMIT() asm volatile("cp.async.commit_group;")
#define CP_WAIT(n)  asm volatile("cp.async.wait_group %0;" :: "n"(n))

#define LDS128(r, addr) \
    asm volatile("ld.shared.v4.b32 {%0,%1,%2,%3}, [%4];" \
                 : "=r"((r)[0]), "=r"((r)[1]), "=r"((r)[2]), "=r"((r)[3]) \
                 : "r"(addr))

__device__ __forceinline__ void mma_f16(float c[4], uint32_t a0, uint32_t a1,
                                        uint32_t a2, uint32_t a3,
                                        uint32_t b0, uint32_t b1) {
    asm volatile(
        "mma.sync.aligned.m16n8k16.row.col.f32.f16.f16.f32 "
        "{%0,%1,%2,%3}, {%4,%5,%6,%7}, {%8,%9}, {%0,%1,%2,%3};"
        : "+f"(c[0]), "+f"(c[1]), "+f"(c[2]), "+f"(c[3])
        : "r"(a0), "r"(a1), "r"(a2), "r"(a3), "r"(b0), "r"(b1));
}

__device__ __forceinline__ void acc_edge(float4 xv, float4 rv, float w,
                                         float4& s, float4& q, float4& mx, float4& mn) {
    float m;
    m = xv.x * rv.x * w; s.x += m; q.x += m * m; mx.x = fmaxf(mx.x, m); mn.x = fminf(mn.x, m);
    m = xv.y * rv.y * w; s.y += m; q.y += m * m; mx.y = fmaxf(mx.y, m); mn.y = fminf(mn.y, m);
    m = xv.z * rv.z * w; s.z += m; q.z += m * m; mx.z = fmaxf(mx.z, m); mn.z = fminf(mn.z, m);
    m = xv.w * rv.w * w; s.w += m; q.w += m * m; mx.w = fmaxf(mx.w, m); mn.w = fminf(mn.w, m);
}

__device__ __forceinline__ float4 h4_to_f4(uint2 u) {
    float2 a = __half22float2(*(__half2*)&u.x);
    float2 b = __half22float2(*(__half2*)&u.y);
    return make_float4(a.x, a.y, b.x, b.y);
}

// ---------------- setup kernels ----------------
// merged: weight transpose/permute + rel_w permute + degree count.
// g_deg zeroing: load-time zero init (run 1) + re-zero at end of k_score (runs 2+).
__global__ void k_transW(const float* __restrict__ W, const float* __restrict__ relw,
                         const int* __restrict__ ei) {
    int idx = blockIdx.x * blockDim.x + threadIdx.x;
    if (idx < NE) atomicAdd(&g_deg[ei[NE + idx]], 1);
    if (idx < 4 * NRL * 128) {
        int pos = idx & 127, tt = idx >> 7;
        int p = pos & 31, c = pos >> 5;
        int lsrc = 2 * (p >> 3) + 8 * ((p & 7) >> 1) + (p & 1);
        g_relP[idx] = relw[tt * 128 + c * 32 + lsrc];
    }
    if (idx < 4 * WN) {
        int l = idx / WN, r = idx - l * WN;
        int n = r / KD, kk = r - n * KD;
        int base = kk & ~31, p = kk & 31;
        int lsrc = 2 * (p >> 3) + 8 * ((p & 7) >> 1) + (p & 1);  // inverse perm
        g_Wt[idx] = __float2half_rn(W[(size_t)l * WN + (size_t)(base + lsrc) * 128 + n]);
    }
}

__global__ void k_scan() {
    __shared__ int wsum[32];
    __shared__ int srun;
    __shared__ float fw[32];
    int tid = threadIdx.x, lane = tid & 31, wid = tid >> 5;
    if (tid == 0) srun = 0;
    float logacc = 0.f;
    for (int base = 0; base < NN; base += 1024) {
        __syncthreads();
        int run = srun;
        int i = base + tid;
        int v = (i < NN) ? g_deg[i] : 0;
        if (i < NN) logacc += logf((float)v + 1.0f);
        int xin = v;
        #pragma unroll
        for (int off = 1; off < 32; off <<= 1) {
            int y = __shfl_up_sync(FULL, xin, off);
            if (lane >= off) xin += y;
        }
        if (lane == 31) wsum[wid] = xin;
        __syncthreads();
        if (wid == 0) {
            int w = wsum[lane];
            #pragma unroll
            for (int off = 1; off < 32; off <<= 1) {
                int y = __shfl_up_sync(FULL, w, off);
                if (lane >= off) w += y;
            }
            wsum[lane] = w;
        }
        __syncthreads();
        int woff = wid ? wsum[wid - 1] : 0;
        int excl = run + woff + xin - v;
        if (i < NN) { g_rowptr[i] = excl; g_cursor[i] = excl; }
        if (tid == 0) srun = run + wsum[31];
    }
    __syncthreads();
    if (tid == 0) g_rowptr[NN] = srun;
    #pragma unroll
    for (int off = 16; off; off >>= 1) logacc += __shfl_xor_sync(FULL, logacc, off);
    if (lane == 0) fw[wid] = logacc;
    __syncthreads();
    if (tid == 0) {
        float t = 0.f;
        for (int i = 0; i < 32; i++) t += fw[i];
        g_logmean = t / (float)NN;
    }
}

// merged: CSR scatter + x0 -> g_xp/g_x0p fp16 permute. grid covers NN*32 threads.
__global__ void k_scatter(const int* __restrict__ ei, const int* __restrict__ et,
                          const float* __restrict__ ew, const float* __restrict__ x0) {
    int idx = blockIdx.x * blockDim.x + threadIdx.x;
    if (idx < NE) {
        int d = ei[NE + idx];
        int pos = atomicAdd(&g_cursor[d], 1);
        g_csr_st[pos] = make_int2(ei[idx], et[idx]);
        g_csr_w[pos]  = ew[idx];
    }
    // permute x0 (idx < NN*32 always true for this grid)
    int node = idx >> 5, m32 = idx & 31;
    if (node < NN) {
        float4 v = ((const float4*)x0)[(size_t)node * 32 + m32];
        int chunk = m32 >> 3, m = m32 & 7;
        int p0 = 16 * (m & 1) + 2 * (m >> 1);
        __half2 lo = __floats2half2_rn(v.x, v.y);
        __half2 hi = __floats2half2_rn(v.z, v.w);
        __half2* dst  = (__half2*)(g_xp + (size_t)node * 128 + chunk * 32);
        __half2* dst0 = (__half2*)(g_x0p + (size_t)node * 128 + chunk * 32);
        dst[p0 >> 1]        = lo;  dst[(p0 >> 1) + 4]  = hi;
        dst0[p0 >> 1]       = lo;  dst0[(p0 >> 1) + 4] = hi;
    }
}

// ---------------- per-layer aggregation: one warp per dst node ----------------
// gathers permuted fp16 x (g_xp) + permuted rel_w; writes g_featsP (permuted fp16)
__global__ void k_agg(const float* __restrict__ relP) {
    int gw = (blockIdx.x * blockDim.x + threadIdx.x) >> 5;
    int lane = threadIdx.x & 31;
    if (gw >= NN) return;
    int off = lane * 4;   // 4 permuted dims per lane

    float4 b = h4_to_f4(*(const uint2*)(g_x0p + (size_t)gw * 128 + off));
    float4 s = b;
    float4 q = make_float4(b.x * b.x, b.y * b.y, b.z * b.z, b.w * b.w);
    float4 mx = b, mn = b;
    int e0 = g_rowptr[gw], e1 = g_rowptr[gw + 1];
    int e = e0;
    for (; e + 3 < e1; e += 4) {
        int2 st0 = g_csr_st[e];     float w0 = g_csr_w[e];
        int2 st1 = g_csr_st[e + 1]; float w1 = g_csr_w[e + 1];
        int2 st2 = g_csr_st[e + 2]; float w2 = g_csr_w[e + 2];
        int2 st3 = g_csr_st[e + 3]; float w3 = g_csr_w[e + 3];
        uint2 ua = *(const uint2*)(g_xp + (size_t)st0.x * 128 + off);
        uint2 ub = *(const uint2*)(g_xp + (size_t)st1.x * 128 + off);
        uint2 uc = *(const uint2*)(g_xp + (size_t)st2.x * 128 + off);
        uint2 ud = *(const uint2*)(g_xp + (size_t)st3.x * 128 + off);
        float4 ra = *(const float4*)(relP + st0.y * 128 + off);
        float4 rb = *(const float4*)(relP + st1.y * 128 + off);
        float4 rc = *(const float4*)(relP + st2.y * 128 + off);
        float4 rd = *(const float4*)(relP + st3.y * 128 + off);
        acc_edge(h4_to_f4(ua), ra, w0, s, q, mx, mn);
        acc_edge(h4_to_f4(ub), rb, w1, s, q, mx, mn);
        acc_edge(h4_to_f4(uc), rc, w2, s, q, mx, mn);
        acc_edge(h4_to_f4(ud), rd, w3, s, q, mx, mn);
    }
    for (; e < e1; e++) {
        int2 st0 = g_csr_st[e]; float w0 = g_csr_w[e];
        uint2 ua = *(const uint2*)(g_xp + (size_t)st0.x * 128 + off);
        float4 ra = *(const float4*)(relP + st0.y * 128 + off);
        acc_edge(h4_to_f4(ua), ra, w0, s, q, mx, mn);
    }
    int degn = e1 - e0;
    float inv = 1.0f / ((float)degn + 1.0f);
    float4 mean = make_float4(s.x * inv, s.y * inv, s.z * inv, s.w * inv);
    float4 sqm  = make_float4(q.x * inv, q.y * inv, q.z * inv, q.w * inv);
    float4 sd;
    sd.x = sqrtf(fmaxf(sqm.x - mean.x * mean.x, 1e-6f));
    sd.y = sqrtf(fmaxf(sqm.y - mean.y * mean.y, 1e-6f));
    sd.z = sqrtf(fmaxf(sqm.z - mean.z * mean.z, 1e-6f));
    sd.w = sqrtf(fmaxf(sqm.w - mean.w * mean.w, 1e-6f));

    float lg = logf((float)degn + 1.0f) / g_logmean;
    float scv[3] = {1.0f, lg, 1.0f / fmaxf(lg, 1e-2f)};
    float4 feats[4] = {mean, mx, mn, sd};

    int cl = lane >> 3, wo = (lane & 7) * 4;     // chunk row + within-chunk offset
    __half* basep = g_featsP + (size_t)gw * 1536;
    #pragma unroll
    for (int ss = 0; ss < 3; ss++) {
        float sc = scv[ss];
        #pragma unroll
        for (int f = 0; f < 4; f++) {
            float4 v = feats[f];
            int chunk = ss * 16 + f * 4 + cl;
            __half2 lo = __floats2half2_rn(v.x * sc, v.y * sc);
            __half2 hi = __floats2half2_rn(v.z * sc, v.w * sc);
            uint2 pk;
            pk.x = *(uint32_t*)&lo; pk.y = *(uint32_t*)&hi;
            *(uint2*)(basep + chunk * 32 + wo) = pk;
        }
    }
}

// ---------------- fp16 mma GEMM + bias + LN + ReLU + residual ----------------
static const int STG_B   = 8192;                 // one stage: 128 rows x 64B
static const int OFF_BST = 4 * STG_B;            // 32768: B stages
static const int OFF_BIAS = 8 * STG_B;           // 65536
static const int OFF_G    = OFF_BIAS + 512;
static const int OFF_BT   = OFF_G + 512;
static const int OFF_R1   = OFF_BT + 512;        // 256 f32
static const int OFF_R2   = OFF_R1 + 1024;
static const int SMEM_BYTES = OFF_R2 + 1024;     // 69120

__global__ void __launch_bounds__(256, 2) k_gemm(const __half* __restrict__ Wt,
                                                 const float* __restrict__ bias,
                                                 const float* __restrict__ gamma,
                                                 const float* __restrict__ beta,
                                                 const float* __restrict__ xin,
                                                 int write_xp) {
    extern __shared__ __align__(128) char smc[];
    uint32_t sbase = (uint32_t)__cvta_generic_to_shared(smc);
    int tid = threadIdx.x, wid = tid >> 5, lane = tid & 31;
    int g = lane >> 2, t4 = lane & 3;
    int wm = wid >> 1, wn = wid & 1;
    int bm = blockIdx.x * 128;

    float* sBias = (float*)(smc + OFF_BIAS);
    float* sG    = (float*)(smc + OFF_G);
    float* sBt   = (float*)(smc + OFF_BT);
    float* red1  = (float*)(smc + OFF_R1);
    float* red2  = (float*)(smc + OFF_R2);
    if (tid < 128) { sBias[tid] = bias[tid]; sG[tid] = gamma[tid]; sBt[tid] = beta[tid]; }

    float acc[2][8][4];
    #pragma unroll
    for (int mt = 0; mt < 2; mt++)
        #pragma unroll
        for (int nt = 0; nt < 8; nt++)
            #pragma unroll
            for (int c = 0; c < 4; c++) acc[mt][nt][c] = 0.f;

    auto issueA = [&](int kt) {
        char* dst = smc + (kt & 3) * STG_B;
        #pragma unroll
        for (int qq = 0; qq < 2; qq++) {
            int c = tid + qq * 256;
            int row = c >> 2, cc = c & 3;
            int gr = bm + row;
            bool ok = gr < NN;
            int rn = ok ? gr : 0;
            const char* src;
            if (kt < 48) src = (const char*)(g_featsP + (size_t)rn * 1536) + kt * 64 + cc * 16;
            else         src = (const char*)(g_xp + (size_t)rn * 128) + (kt - 48) * 64 + cc * 16;
            cp16z(dst + c * 16, src, ok ? 16 : 0);
        }
    };
    auto issueB = [&](int kt) {
        char* dst = smc + OFF_BST + (kt & 3) * STG_B;
        #pragma unroll
        for (int qq = 0; qq < 2; qq++) {
            int c = tid + qq * 256;
            int n = c >> 2, cc = c & 3;
            const char* src = (const char*)(Wt + (size_t)n * KD) + kt * 64 + cc * 16;
            cp16z(dst + c * 16, src, 16);
        }
    };

    issueA(0); issueB(0); CP_COMMIT();
    issueA(1); issueB(1); CP_COMMIT();
    issueA(2); issueB(2); CP_COMMIT();

    for (int kt = 0; kt < 52; kt++) {
        if (kt <= 49)      { CP_WAIT(2); }
        else if (kt == 50) { CP_WAIT(1); }
        else               { CP_WAIT(0); }
        __syncthreads();
        if (kt + 3 < 52) { issueA(kt + 3); issueB(kt + 3); CP_COMMIT(); }

        uint32_t Au = sbase + (kt & 3) * STG_B;
        uint32_t Bu = sbase + OFF_BST + (kt & 3) * STG_B;
        uint32_t raf[2][2][4];
        #pragma unroll
        for (int mt = 0; mt < 2; mt++)
            #pragma unroll
            for (int rh = 0; rh < 2; rh++) {
                int row = wm * 32 + mt * 16 + rh * 8 + g;
                LDS128(raf[mt][rh], Au + row * 64 + t4 * 16);
            }
        #pragma unroll
        for (int nt = 0; nt < 8; nt++) {
            uint32_t bb[4];
            int c0 = wn * 64 + nt * 8 + g;
            LDS128(bb, Bu + c0 * 64 + t4 * 16);
            #pragma unroll
            for (int mt = 0; mt < 2; mt++) {
                mma_f16(acc[mt][nt], raf[mt][0][0], raf[mt][1][0],
                        raf[mt][0][1], raf[mt][1][1], bb[0], bb[1]);
                mma_f16(acc[mt][nt], raf[mt][0][2], raf[mt][1][2],
                        raf[mt][0][3], raf[mt][1][3], bb[2], bb[3]);
            }
        }
    }
    __syncthreads();

    // ---- epilogue: +bias, LayerNorm(128), ReLU, residual; write g_x + g_xp ----
    #pragma unroll
    for (int mt = 0; mt < 2; mt++)
        #pragma unroll
        for (int nt = 0; nt < 8; nt++)
            #pragma unroll
            for (int c = 0; c < 4; c++) {
                int col = wn * 64 + nt * 8 + 2 * t4 + (c & 1);
                acc[mt][nt][c] += sBias[col];
            }
    #pragma unroll
    for (int mt = 0; mt < 2; mt++)
        #pragma unroll
        for (int h = 0; h < 2; h++) {
            float S1 = 0.f, S2 = 0.f;
            #pragma unroll
            for (int nt = 0; nt < 8; nt++) {
                float v0 = acc[mt][nt][2 * h], v1 = acc[mt][nt][2 * h + 1];
                S1 += v0 + v1; S2 += v0 * v0 + v1 * v1;
            }
            S1 += __shfl_xor_sync(FULL, S1, 1); S2 += __shfl_xor_sync(FULL, S2, 1);
            S1 += __shfl_xor_sync(FULL, S1, 2); S2 += __shfl_xor_sync(FULL, S2, 2);
            if (t4 == 0) {
                int rl = wm * 32 + mt * 16 + h * 8 + g;
                red1[wn * 128 + rl] = S1; red2[wn * 128 + rl] = S2;
            }
        }
    __syncthreads();
    #pragma unroll
    for (int mt = 0; mt < 2; mt++)
        #pragma unroll
        for (int h = 0; h < 2; h++) {
            int rl = wm * 32 + mt * 16 + h * 8 + g;
            int grow = bm + rl;
            float T1 = red1[rl] + red1[128 + rl];
            float T2 = red2[rl] + red2[128 + rl];
            float mean = T1 * (1.0f / 128.0f);
            float var  = T2 * (1.0f / 128.0f) - mean * mean;
            float rstd = rsqrtf(var + 1e-5f);
            if (grow < NN) {
                #pragma unroll
                for (int nt = 0; nt < 8; nt++) {
                    int col = wn * 64 + nt * 8 + 2 * t4;
                    float v0 = (acc[mt][nt][2 * h] - mean) * rstd * sG[col] + sBt[col];
                    float v1 = (acc[mt][nt][2 * h + 1] - mean) * rstd * sG[col + 1] + sBt[col + 1];
                    v0 = fmaxf(v0, 0.f); v1 = fmaxf(v1, 0.f);
                    float2 xv = *(const float2*)(xin + (size_t)grow * 128 + col);
                    v0 += xv.x; v1 += xv.y;
                    *(float2*)(g_x + (size_t)grow * 128 + col) = make_float2(v0, v1);
                    if (write_xp) {
                        int chunk = wn * 2 + (nt >> 2);
                        int pb = t4 * 8 + (nt & 3) * 2;
                        ((__half2*)(g_xp + (size_t)grow * 128 + chunk * 32))[pb >> 1] =
                            __floats2half2_rn(v0, v1);
                    }
                }
            }
        }
}

// ---------------- distmult scoring (+ re-zero g_deg for next run) ----------------
__global__ void k_score(const float* __restrict__ qw, const int* __restrict__ src,
                        const int* __restrict__ rel, const int* __restrict__ dst,
                        float* __restrict__ out) {
    int tidg = blockIdx.x * blockDim.x + threadIdx.x;
    if (tidg < NN) g_deg[tidg] = 0;   // deterministic re-zero for next pass
    int gw = tidg >> 5;
    int lane = threadIdx.x & 31;
    if (gw >= BQ * KQ) return;
    int si = src[gw], ri = rel[gw], di = dst[gw];
    const float4* X = (const float4*)g_x;
    const float4* Q = (const float4*)qw;
    float4 a = X[(size_t)si * 32 + lane], q = Q[ri * 32 + lane], b = X[(size_t)di * 32 + lane];
    float v = a.x * q.x * b.x + a.y * q.y * b.y + a.z * q.z * b.z + a.w * q.w * b.w;
    #pragma unroll
    for (int off = 16; off; off >>= 1) v += __shfl_xor_sync(FULL, v, off);
    if (lane == 0) out[gw] = v;
}

// ---------------- launch ----------------
extern "C" void kernel_launch(void* const* d_in, const int* in_sizes, int n_in,
                              void* d_out, int out_size) {
    const float* x0     = (const float*)d_in[0];
    const int*   ei     = (const int*)d_in[1];
    const int*   etype  = (const int*)d_in[2];
    const float* ew     = (const float*)d_in[3];
    const float* rel_w  = (const float*)d_in[4];
    const float* lin_w  = (const float*)d_in[5];
    const float* lin_b  = (const float*)d_in[6];
    const float* ln_g   = (const float*)d_in[7];
    const float* ln_b   = (const float*)d_in[8];
    const float* qw     = (const float*)d_in[9];
    const int*   src    = (const int*)d_in[10];
    const int*   rel    = (const int*)d_in[11];
    const int*   dst    = (const int*)d_in[12];
    float* out = (float*)d_out;

    cudaFuncSetAttribute(k_gemm, cudaFuncAttributeMaxDynamicSharedMemorySize, SMEM_BYTES);

    __half* wt_dev = nullptr;
    float*  gx_dev = nullptr;
    float*  relp_dev = nullptr;
    cudaGetSymbolAddress((void**)&wt_dev, g_Wt);
    cudaGetSymbolAddress((void**)&gx_dev, g_x);
    cudaGetSymbolAddress((void**)&relp_dev, g_relP);

    k_transW<<<(4 * WN + 255) / 256, 256>>>(lin_w, rel_w, ei);        // + deg count
    k_scan<<<1, 1024>>>();
    k_scatter<<<(NN * 32) / 256, 256>>>(ei, etype, ew, x0);           // + x0 permute

    for (int l = 0; l < 4; l++) {
        const float* xin = (l == 0) ? x0 : gx_dev;
        k_agg<<<NN / 8, 256>>>(relp_dev + (size_t)l * NRL * 128);
        k_gemm<<<(NN + 127) / 128, 256, SMEM_BYTES>>>(
            wt_dev + (size_t)l * WN,
            lin_b + (size_t)l * D,
            ln_g + (size_t)l * D,
            ln_b + (size_t)l * D,
            xin,
            (l < 3) ? 1 : 0);
    }
    k_score<<<(BQ * KQ) / 8, 256>>>(qw, src, rel, dst, out);
}